// round 2
// baseline (speedup 1.0000x reference)
#include <cuda_runtime.h>
#include <math.h>

#define NN 50000
#define EE 1600000

// ---------------- scratch (device globals; no allocation allowed) ----------------
__device__ __align__(16) float g_xl[NN * 64];     // x_local @ gat_w^T
__device__ __align__(16) float g_xg[NN * 64];     // x_global @ gcn_w^T
__device__ __align__(16) float g_gat[NN * 64];    // final x_l
__device__ __align__(16) float g_gcn[NN * 64];    // final x_g
__device__ float g_asrc[NN];
__device__ float g_adst[NN];
__device__ float g_nind[NN];
__device__ float g_den[NN];
__device__ float g_deg[NN];
__device__ float g_dis[NN];
__device__ float g_exself[NN];
__device__ int   g_cnt[NN];        // per-dst edge count
__device__ int   g_start[NN];      // exclusive scan of cnt
__device__ int   g_cursor[NN];     // running insert position
__device__ int   g_bsum[64];       // block sums for scan
__device__ int   g_boff[64];       // scanned block sums
__device__ __align__(16) float4 g_edata[EE];  // {src_bits, ex, ew, pad} binned by dst

__device__ __forceinline__ float elu1(float v) { return v > 0.f ? v : (expf(v) - 1.f); }

// ---------------- per-node noise MLP ----------------
__global__ void k_nind(const float* __restrict__ nf, const float* __restrict__ fc1w,
                       const float* __restrict__ fc1b, const float* __restrict__ fc2w,
                       const float* __restrict__ fc2b) {
    __shared__ float w1[100], b1[10], w2[10], b2s;
    int tid = threadIdx.x;
    if (tid < 100) w1[tid] = fc1w[tid];
    if (tid < 10) { b1[tid] = fc1b[tid]; w2[tid] = fc2w[tid]; }
    if (tid == 0) b2s = fc2b[0];
    __syncthreads();
    int i = blockIdx.x * blockDim.x + tid;
    if (i >= NN) return;
    float x[10];
#pragma unroll
    for (int k = 0; k < 10; k++) x[k] = nf[i * 10 + k];
    float acc = b2s;
#pragma unroll
    for (int j = 0; j < 10; j++) {
        float h = b1[j];
#pragma unroll
        for (int k = 0; k < 10; k++) h += x[k] * w1[j * 10 + k];
        h = elu1(h);
        acc += h * w2[j];
    }
    g_nind[i] = acc;
}

// ---------------- GEMM: out[n][64] = sum_k X[n][k] * W[h][k]   (K=128, H=64) ----------------
__global__ void k_gemm(const float* __restrict__ X, const float* __restrict__ W,
                       float* __restrict__ out, int nrows) {
    extern __shared__ float sm[];
    float (*Xs)[68] = (float(*)[68])sm;
    float (*Ws)[68] = (float(*)[68])(sm + 128 * 68);
    int tid = threadIdx.x;
    int r0 = blockIdx.x * 64;
#pragma unroll
    for (int i = 0; i < 32; i++) {
        int idx = tid + i * 256;
        int h = idx >> 7, k = idx & 127;
        Ws[k][h] = W[idx];
    }
#pragma unroll
    for (int i = 0; i < 32; i++) {
        int idx = tid + i * 256;
        int n = idx >> 7, k = idx & 127;
        int r = r0 + n;
        Xs[k][n] = (r < nrows) ? X[r * 128 + k] : 0.f;
    }
    __syncthreads();
    int ty = tid >> 4, tx = tid & 15;
    int n0 = ty * 4, h0 = tx * 4;
    float acc[4][4] = {};
#pragma unroll 4
    for (int k = 0; k < 128; k++) {
        float4 xv = *(const float4*)&Xs[k][n0];
        float4 wv = *(const float4*)&Ws[k][h0];
        float xs[4] = {xv.x, xv.y, xv.z, xv.w};
        float ws[4] = {wv.x, wv.y, wv.z, wv.w};
#pragma unroll
        for (int i = 0; i < 4; i++)
#pragma unroll
            for (int j = 0; j < 4; j++) acc[i][j] += xs[i] * ws[j];
    }
#pragma unroll
    for (int i = 0; i < 4; i++) {
        int r = r0 + n0 + i;
        if (r < nrows) {
            float4 o = make_float4(acc[i][0], acc[i][1], acc[i][2], acc[i][3]);
            *(float4*)&out[r * 64 + h0] = o;
        }
    }
}

// ---------------- per-node attention scalars + self-loop init ----------------
__global__ void k_node_attn(const float* __restrict__ att_s, const float* __restrict__ att_d) {
    __shared__ float ss[64], sd[64];
    int tid = threadIdx.x;
    if (tid < 64) { ss[tid] = att_s[tid]; sd[tid] = att_d[tid]; }
    __syncthreads();
    int i = blockIdx.x * blockDim.x + tid;
    if (i >= NN) return;
    const float4* row = (const float4*)(g_xl + i * 64);
    float a = 0.f, b = 0.f;
#pragma unroll
    for (int j = 0; j < 16; j++) {
        float4 v = row[j];
        a += v.x * ss[4 * j] + v.y * ss[4 * j + 1] + v.z * ss[4 * j + 2] + v.w * ss[4 * j + 3];
        b += v.x * sd[4 * j] + v.y * sd[4 * j + 1] + v.z * sd[4 * j + 2] + v.w * sd[4 * j + 3];
    }
    g_asrc[i] = a;
    g_adst[i] = b;
    float e = a + b;
    e = e > 0.f ? e : 0.2f * e;
    float ex = expf(e);
    g_exself[i] = ex;
    g_den[i] = ex;
    g_deg[i] = 1.f;
}

// ---------------- histogram over dst ----------------
__global__ void k_hist(const int* __restrict__ ei) {
    int t = blockIdx.x * blockDim.x + threadIdx.x;
    if (t < EE) atomicAdd(&g_cnt[ei[EE + t]], 1);
}

// ---------------- 3-kernel exclusive scan of g_cnt -> g_start ----------------
__global__ void k_scan1() {   // grid 49, block 256; 1024 elems/block
    __shared__ int wsum[8], woff[8];
    int tid = threadIdx.x, lane = tid & 31, wrp = tid >> 5;
    int base = blockIdx.x * 1024 + tid * 4;
    int c0 = 0, c1 = 0, c2 = 0, c3 = 0;
    if (base + 0 < NN) c0 = g_cnt[base + 0];
    if (base + 1 < NN) c1 = g_cnt[base + 1];
    if (base + 2 < NN) c2 = g_cnt[base + 2];
    if (base + 3 < NN) c3 = g_cnt[base + 3];
    int tot = c0 + c1 + c2 + c3;
    int v = tot;
#pragma unroll
    for (int off = 1; off < 32; off <<= 1) {
        int o = __shfl_up_sync(~0u, v, off);
        if (lane >= off) v += o;
    }
    if (lane == 31) wsum[wrp] = v;
    __syncthreads();
    if (wrp == 0 && lane < 8) {
        int w = wsum[lane], iv = w;
#pragma unroll
        for (int off = 1; off < 8; off <<= 1) {
            int o = __shfl_up_sync(0xffu, iv, off);
            if (lane >= off) iv += o;
        }
        woff[lane] = iv - w;
    }
    __syncthreads();
    int excl = (v - tot) + woff[wrp];
    if (base + 0 < NN) g_start[base + 0] = excl;
    if (base + 1 < NN) g_start[base + 1] = excl + c0;
    if (base + 2 < NN) g_start[base + 2] = excl + c0 + c1;
    if (base + 3 < NN) g_start[base + 3] = excl + c0 + c1 + c2;
    if (tid == 255) g_bsum[blockIdx.x] = excl + tot;
}
__global__ void k_scan2(int nblk) {  // 1 thread
    int run = 0;
    for (int i = 0; i < nblk; i++) { g_boff[i] = run; run += g_bsum[i]; }
}
__global__ void k_scan3() {
    int i = blockIdx.x * blockDim.x + threadIdx.x;
    if (i >= NN) return;
    int s = g_start[i] + g_boff[i >> 10];
    g_start[i] = s;
    g_cursor[i] = s;
}

// ---------------- edge scalar pass: ex/ew, den/deg atomics, binned record write --------
__global__ void k_edge_scalar(const int* __restrict__ ei, const float* __restrict__ coord) {
    int t = blockIdx.x * blockDim.x + threadIdx.x;
    if (t >= EE) return;
    int s = ei[t], d = ei[EE + t];
    float ni = g_nind[s];
    float2 cs = ((const float2*)coord)[s];
    float2 cd = ((const float2*)coord)[d];
    float dx = cs.x - cd.x, dy = cs.y - cd.y;
    float gw = expf(-(dx * dx + dy * dy) * (1.0f / 1800.0f));
    float z = gw * (1.f + ni) - 1.f;
    float w = 0.1f + 1.9f / (1.f + expf(-z));
    bool m = (w >= 0.2f);
    float e = g_asrc[s] + g_adst[d];
    e = e > 0.f ? e : 0.2f * e;
    float ex = m ? expf(e) : 0.f;
    float ew = m ? w : 0.f;
    if (m) {
        atomicAdd(&g_den[d], ex);
        atomicAdd(&g_deg[d], ew);
    }
    int pos = atomicAdd(&g_cursor[d], 1);
    g_edata[pos] = make_float4(__int_as_float(s), ex, ew, 0.f);
}

// ---------------- dis = rsqrt(deg) ----------------
__global__ void k_dis() {
    int i = blockIdx.x * blockDim.x + threadIdx.x;
    if (i >= NN) return;
    g_dis[i] = rsqrtf(g_deg[i]);
}

// ---------------- gather-side reduce: one warp per dst node, fused finalize --------
__global__ void k_reduce(const float* __restrict__ gat_b, const float* __restrict__ gcn_b) {
    int n = (blockIdx.x * blockDim.x + threadIdx.x) >> 5;
    if (n >= NN) return;
    int lane = threadIdx.x & 31;
    bool isG = lane >= 16;
    int l = lane & 15;
    const float4* feat = isG ? (const float4*)g_xg : (const float4*)g_xl;
    int beg = g_start[n], cnt = g_cnt[n];
    float4 acc = make_float4(0.f, 0.f, 0.f, 0.f);
    for (int base = 0; base < cnt; base += 32) {
        int e = base + lane;
        float4 ed = make_float4(0.f, 0.f, 0.f, 0.f);
        if (e < cnt) ed = g_edata[beg + e];
        int s_l = __float_as_int(ed.x);
        float ex_l = ed.y;
        float ewd_l = ed.z * g_dis[s_l];   // ed.x=0 when invalid -> harmless dis[0] read
        int m = min(32, cnt - base);
        for (int j = 0; j < m; j++) {
            int s = __shfl_sync(~0u, s_l, j);
            float ex = __shfl_sync(~0u, ex_l, j);
            float ewd = __shfl_sync(~0u, ewd_l, j);
            if (ex == 0.f && ewd == 0.f) continue;   // masked edge, uniform across warp
            float wgt = isG ? ewd : ex;
            float4 v = feat[s * 16 + l];
            acc.x += wgt * v.x; acc.y += wgt * v.y;
            acc.z += wgt * v.z; acc.w += wgt * v.w;
        }
    }
    float4 vs = feat[n * 16 + l];
    if (!isG) {
        float exs = g_exself[n];
        float inv = 1.f / g_den[n];
        float4 b = ((const float4*)gat_b)[l];
        float4 r;
        r.x = elu1((acc.x + exs * vs.x) * inv + b.x);
        r.y = elu1((acc.y + exs * vs.y) * inv + b.y);
        r.z = elu1((acc.z + exs * vs.z) * inv + b.z);
        r.w = elu1((acc.w + exs * vs.w) * inv + b.w);
        ((float4*)g_gat)[n * 16 + l] = r;
    } else {
        float dis = g_dis[n];
        float4 b = ((const float4*)gcn_b)[l];
        float4 q;
        q.x = fmaxf(dis * (acc.x + dis * vs.x) + b.x, 0.f);
        q.y = fmaxf(dis * (acc.y + dis * vs.y) + b.y, 0.f);
        q.z = fmaxf(dis * (acc.z + dis * vs.z) + b.z, 0.f);
        q.w = fmaxf(dis * (acc.w + dis * vs.w) + b.w, 0.f);
        ((float4*)g_gcn)[n * 16 + l] = q;
    }
}

// ---------------- fusion: out = w2 @ relu(W1 @ [x_l; x_g] + b1) + b2 ----------------
__global__ void k_fusion(const float* __restrict__ W1, const float* __restrict__ b1,
                         const float* __restrict__ w2, const float* __restrict__ b2,
                         float* __restrict__ out, int nrows) {
    extern __shared__ float sm[];
    float (*Xs)[68] = (float(*)[68])sm;
    float (*Ws)[68] = (float(*)[68])(sm + 128 * 68);
    int tid = threadIdx.x;
    int r0 = blockIdx.x * 64;
#pragma unroll
    for (int i = 0; i < 32; i++) {
        int idx = tid + i * 256;
        int h = idx >> 7, k = idx & 127;
        Ws[k][h] = W1[idx];
    }
#pragma unroll
    for (int i = 0; i < 32; i++) {
        int idx = tid + i * 256;
        int n = idx >> 7, k = idx & 127;
        int r = r0 + n;
        float v = 0.f;
        if (r < nrows) v = (k < 64) ? g_gat[r * 64 + k] : g_gcn[r * 64 + (k - 64)];
        Xs[k][n] = v;
    }
    __syncthreads();
    int ty = tid >> 4, tx = tid & 15;
    int n0 = ty * 4, h0 = tx * 4;
    float acc[4][4] = {};
#pragma unroll 4
    for (int k = 0; k < 128; k++) {
        float4 xv = *(const float4*)&Xs[k][n0];
        float4 wv = *(const float4*)&Ws[k][h0];
        float xs[4] = {xv.x, xv.y, xv.z, xv.w};
        float ws[4] = {wv.x, wv.y, wv.z, wv.w};
#pragma unroll
        for (int i = 0; i < 4; i++)
#pragma unroll
            for (int j = 0; j < 4; j++) acc[i][j] += xs[i] * ws[j];
    }
    float b1v[4], w2v[4];
#pragma unroll
    for (int j = 0; j < 4; j++) { b1v[j] = b1[h0 + j]; w2v[j] = w2[h0 + j]; }
    float part[4];
#pragma unroll
    for (int i = 0; i < 4; i++) {
        float p = 0.f;
#pragma unroll
        for (int j = 0; j < 4; j++) p += fmaxf(acc[i][j] + b1v[j], 0.f) * w2v[j];
        part[i] = p;
    }
#pragma unroll
    for (int off = 8; off >= 1; off >>= 1)
#pragma unroll
        for (int i = 0; i < 4; i++) part[i] += __shfl_down_sync(0xffffffffu, part[i], off);
    if (tx == 0) {
        float bb = b2[0];
#pragma unroll
        for (int i = 0; i < 4; i++) {
            int r = r0 + n0 + i;
            if (r < nrows) out[r] = part[i] + bb;
        }
    }
}

// ---------------- launch ----------------
extern "C" void kernel_launch(void* const* d_in, const int* in_sizes, int n_in,
                              void* d_out, int out_size) {
    const float* x_local  = (const float*)d_in[0];
    const float* x_global = (const float*)d_in[1];
    const float* nf       = (const float*)d_in[2];
    const float* coord    = (const float*)d_in[3];
    const int*   ei       = (const int*)d_in[4];
    const float* fc1w     = (const float*)d_in[5];
    const float* fc1b     = (const float*)d_in[6];
    const float* fc2w     = (const float*)d_in[7];
    const float* fc2b     = (const float*)d_in[8];
    const float* gat_w    = (const float*)d_in[9];
    const float* att_s    = (const float*)d_in[10];
    const float* att_d    = (const float*)d_in[11];
    const float* gat_b    = (const float*)d_in[12];
    const float* gcn_w    = (const float*)d_in[13];
    const float* gcn_b    = (const float*)d_in[14];
    const float* fus_w1   = (const float*)d_in[15];
    const float* fus_b1   = (const float*)d_in[16];
    const float* fus_w2   = (const float*)d_in[17];
    const float* fus_b2   = (const float*)d_in[18];
    float* out = (float*)d_out;

    const int SMEM = 2 * 128 * 68 * (int)sizeof(float);  // 69632
    cudaFuncSetAttribute(k_gemm,   cudaFuncAttributeMaxDynamicSharedMemorySize, SMEM);
    cudaFuncSetAttribute(k_fusion, cudaFuncAttributeMaxDynamicSharedMemorySize, SMEM);

    float *pxl, *pxg;
    void *pcnt;
    cudaGetSymbolAddress((void**)&pxl, g_xl);
    cudaGetSymbolAddress((void**)&pxg, g_xg);
    cudaGetSymbolAddress(&pcnt, g_cnt);

    const int NB_N   = (NN + 255) / 256;        // 196
    const int NB_E   = (EE + 255) / 256;        // 6250
    const int NB_G   = (NN + 63) / 64;          // 782
    const int NB_R   = (NN * 32 + 255) / 256;   // 6250
    const int NSCAN  = (NN + 1023) / 1024;      // 49

    cudaMemsetAsync(pcnt, 0, NN * sizeof(int));
    k_hist<<<NB_E, 256>>>(ei);
    k_nind<<<NB_N, 256>>>(nf, fc1w, fc1b, fc2w, fc2b);
    k_gemm<<<NB_G, 256, SMEM>>>(x_local, gat_w, pxl, NN);
    k_gemm<<<NB_G, 256, SMEM>>>(x_global, gcn_w, pxg, NN);
    k_node_attn<<<NB_N, 256>>>(att_s, att_d);
    k_scan1<<<NSCAN, 256>>>();
    k_scan2<<<1, 1>>>(NSCAN);
    k_scan3<<<NB_N, 256>>>();
    k_edge_scalar<<<NB_E, 256>>>(ei, coord);
    k_dis<<<NB_N, 256>>>();
    k_reduce<<<NB_R, 256>>>(gat_b, gcn_b);
    k_fusion<<<NB_G, 256, SMEM>>>(fus_w1, fus_b1, fus_w2, fus_b2, out, NN);
}

// round 3
// speedup vs baseline: 1.1642x; 1.1642x over previous
#include <cuda_runtime.h>
#include <cuda_fp16.h>
#include <math.h>

#define NN 50000
#define EE 1600000

// ---------------- scratch (device globals; no allocation allowed) ----------------
__device__ __align__(16) float g_xl[NN * 64];      // x_local @ gat_w^T (fp32)
__device__ __align__(16) float g_xg[NN * 64];      // x_global @ gcn_w^T (fp32)
__device__ __align__(16) __half2 g_xl_h[NN * 32];  // fp16 copy for edge gathers
__device__ __align__(16) __half2 g_xg_h[NN * 32];
__device__ __align__(16) float g_gat[NN * 64];     // GAT edge-numerator accumulator
__device__ __align__(16) float g_gcn[NN * 64];     // GCN edge-numerator accumulator
__device__ float g_asrc[NN];
__device__ float g_adst[NN];
__device__ float g_nind[NN];
__device__ float g_exself[NN];
__device__ float g_den[NN];
__device__ float g_deg[NN];
__device__ float g_dis[NN];
__device__ float g_ex[EE];
__device__ float g_ew[EE];

// ---------------- helpers ----------------
__device__ __forceinline__ void red4(float* p, float a, float b, float c, float d) {
    asm volatile("red.global.add.v4.f32 [%0], {%1,%2,%3,%4};"
                 :: "l"(p), "f"(a), "f"(b), "f"(c), "f"(d) : "memory");
}
__device__ __forceinline__ float elu1(float v) { return v > 0.f ? v : (expf(v) - 1.f); }

// ---------------- GEMM: out[n][64] = sum_k X[n][k] * W[h][k]  (K=128, H=64) -------
// 128 rows/block, 256 threads, 8x4 thread tile. smem 102400 B.
__global__ void k_gemm(const float* __restrict__ X, const float* __restrict__ W,
                       float* __restrict__ out, __half2* __restrict__ outh, int nrows) {
    extern __shared__ float sm[];
    float (*Xs)[132] = (float(*)[132])sm;              // [k][n]
    float (*Ws)[68]  = (float(*)[68])(sm + 128 * 132); // [k][h]
    int tid = threadIdx.x;
    int r0 = blockIdx.x * 128;

    // load X: thread t -> row r = t&127, k-half = t>>7 (64 k each)
    {
        int r = tid & 127, kb = (tid >> 7) * 64;
        int rr = r0 + r;
        const float4* src = (const float4*)(X + (size_t)rr * 128 + kb);
#pragma unroll
        for (int j = 0; j < 16; j++) {
            float4 v = (rr < nrows) ? src[j] : make_float4(0.f, 0.f, 0.f, 0.f);
            int k = kb + 4 * j;
            Xs[k + 0][r] = v.x; Xs[k + 1][r] = v.y;
            Xs[k + 2][r] = v.z; Xs[k + 3][r] = v.w;
        }
    }
    // load W: thread t -> h = t&63, k-quarter = t>>6 (32 k each)
    {
        int h = tid & 63, kb = (tid >> 6) * 32;
        const float4* src = (const float4*)(W + (size_t)h * 128 + kb);
#pragma unroll
        for (int j = 0; j < 8; j++) {
            float4 v = src[j];
            int k = kb + 4 * j;
            Ws[k + 0][h] = v.x; Ws[k + 1][h] = v.y;
            Ws[k + 2][h] = v.z; Ws[k + 3][h] = v.w;
        }
    }
    __syncthreads();

    int ty = tid >> 4, tx = tid & 15;
    int n0 = ty * 8, h0 = tx * 4;
    float acc[8][4] = {};
#pragma unroll 4
    for (int k = 0; k < 128; k++) {
        float4 x0 = *(const float4*)&Xs[k][n0];
        float4 x1 = *(const float4*)&Xs[k][n0 + 4];
        float4 wv = *(const float4*)&Ws[k][h0];
        float xs[8] = {x0.x, x0.y, x0.z, x0.w, x1.x, x1.y, x1.z, x1.w};
        float ws[4] = {wv.x, wv.y, wv.z, wv.w};
#pragma unroll
        for (int i = 0; i < 8; i++)
#pragma unroll
            for (int j = 0; j < 4; j++) acc[i][j] += xs[i] * ws[j];
    }
#pragma unroll
    for (int i = 0; i < 8; i++) {
        int r = r0 + n0 + i;
        if (r < nrows) {
            *(float4*)&out[(size_t)r * 64 + h0] =
                make_float4(acc[i][0], acc[i][1], acc[i][2], acc[i][3]);
            __half2 p0 = __floats2half2_rn(acc[i][0], acc[i][1]);
            __half2 p1 = __floats2half2_rn(acc[i][2], acc[i][3]);
            outh[(size_t)r * 32 + (h0 >> 1)] = p0;
            outh[(size_t)r * 32 + (h0 >> 1) + 1] = p1;
        }
    }
}

// ---------------- per-node: noise MLP + attention scalars + self-loop init --------
__global__ void k_node(const float* __restrict__ nf, const float* __restrict__ fc1w,
                       const float* __restrict__ fc1b, const float* __restrict__ fc2w,
                       const float* __restrict__ fc2b,
                       const float* __restrict__ att_s, const float* __restrict__ att_d) {
    __shared__ float w1[100], b1[10], w2[10], b2s, ss[64], sd[64];
    int tid = threadIdx.x;
    if (tid < 100) w1[tid] = fc1w[tid];
    if (tid < 10) { b1[tid] = fc1b[tid]; w2[tid] = fc2w[tid]; }
    if (tid == 0) b2s = fc2b[0];
    if (tid >= 128 && tid < 192) ss[tid - 128] = att_s[tid - 128];
    if (tid >= 192) sd[tid - 192] = att_d[tid - 192];
    __syncthreads();
    int i = blockIdx.x * blockDim.x + tid;
    if (i >= NN) return;

    // noise MLP
    float x[10];
#pragma unroll
    for (int k = 0; k < 10; k++) x[k] = nf[i * 10 + k];
    float acc = b2s;
#pragma unroll
    for (int j = 0; j < 10; j++) {
        float h = b1[j];
#pragma unroll
        for (int k = 0; k < 10; k++) h += x[k] * w1[j * 10 + k];
        acc += elu1(h) * w2[j];
    }
    g_nind[i] = acc;

    // attention scalars
    const float4* row = (const float4*)(g_xl + (size_t)i * 64);
    float a = 0.f, b = 0.f;
#pragma unroll
    for (int j = 0; j < 16; j++) {
        float4 v = row[j];
        a += v.x * ss[4 * j] + v.y * ss[4 * j + 1] + v.z * ss[4 * j + 2] + v.w * ss[4 * j + 3];
        b += v.x * sd[4 * j] + v.y * sd[4 * j + 1] + v.z * sd[4 * j + 2] + v.w * sd[4 * j + 3];
    }
    g_asrc[i] = a;
    g_adst[i] = b;
    float e = a + b;
    e = e > 0.f ? e : 0.2f * e;
    float ex = expf(e);
    g_exself[i] = ex;
    g_den[i] = ex;   // self-loop contribution
    g_deg[i] = 1.f;  // self-loop weight
}

// ---------------- edge scalar pass: ex/ew + den/deg atomics ----------------
__global__ void k_edge_scalar(const int* __restrict__ ei, const float* __restrict__ coord) {
    int t = blockIdx.x * blockDim.x + threadIdx.x;
    if (t >= EE) return;
    int s = ei[t], d = ei[EE + t];
    float ni = g_nind[s];
    float2 cs = ((const float2*)coord)[s];
    float2 cd = ((const float2*)coord)[d];
    float dx = cs.x - cd.x, dy = cs.y - cd.y;
    float gw = expf(-(dx * dx + dy * dy) * (1.0f / 1800.0f));
    float z = gw * (1.f + ni) - 1.f;
    float w = 0.1f + 1.9f / (1.f + expf(-z));
    bool m = (w >= 0.2f);
    float e = g_asrc[s] + g_adst[d];
    e = e > 0.f ? e : 0.2f * e;
    float ex = m ? expf(e) : 0.f;
    float ew = m ? w : 0.f;
    g_ex[t] = ex;
    g_ew[t] = ew;
    if (m) {
        atomicAdd(&g_den[d], ex);
        atomicAdd(&g_deg[d], ew);
    }
}

// ---------------- dis = rsqrt(deg) ----------------
__global__ void k_dis() {
    int i = blockIdx.x * blockDim.x + threadIdx.x;
    if (i < NN) g_dis[i] = rsqrtf(g_deg[i]);
}

// ---------------- vector edge pass: fp16 gathers, fp32 red scatter ----------------
__global__ void k_edge_vec(const int* __restrict__ ei) {
    int gt = blockIdx.x * blockDim.x + threadIdx.x;
    int t = gt >> 4;
    if (t >= EE) return;
    float ew = g_ew[t];
    if (ew == 0.f) return;  // masked edge (uniform across the 16-thread group)
    int l = gt & 15;
    int s = ei[t], d = ei[EE + t];
    float ex = g_ex[t];
    float c = ew * g_dis[s];

    const __half2* pl = &g_xl_h[(size_t)s * 32 + 2 * l];
    __half2 a0 = pl[0], a1 = pl[1];
    float2 f0 = __half22float2(a0), f1 = __half22float2(a1);
    red4(&g_gat[(size_t)d * 64 + 4 * l], ex * f0.x, ex * f0.y, ex * f1.x, ex * f1.y);

    const __half2* pg = &g_xg_h[(size_t)s * 32 + 2 * l];
    __half2 b0 = pg[0], b1 = pg[1];
    float2 u0 = __half22float2(b0), u1 = __half22float2(b1);
    red4(&g_gcn[(size_t)d * 64 + 4 * l], c * u0.x, c * u0.y, c * u1.x, c * u1.y);
}

// ---------------- fusion: finalize both branches inline + MLP head ----------------
__global__ void k_fusion(const float* __restrict__ W1, const float* __restrict__ b1,
                         const float* __restrict__ w2, const float* __restrict__ b2,
                         const float* __restrict__ gat_b, const float* __restrict__ gcn_b,
                         float* __restrict__ out, int nrows) {
    extern __shared__ float sm[];
    float (*Xs)[68] = (float(*)[68])sm;
    float (*Ws)[68] = (float(*)[68])(sm + 128 * 68);
    int tid = threadIdx.x;
    int r0 = blockIdx.x * 64;
#pragma unroll
    for (int i = 0; i < 32; i++) {
        int idx = tid + i * 256;
        int h = idx >> 7, k = idx & 127;
        Ws[k][h] = W1[idx];
    }
#pragma unroll
    for (int i = 0; i < 32; i++) {
        int idx = tid + i * 256;
        int n = idx >> 7, k = idx & 127;
        int r = r0 + n;
        float v = 0.f;
        if (r < nrows) {
            if (k < 64) {  // GAT branch finalize: elu((acc + exself*xl)/den + b)
                float inv = 1.f / g_den[r];
                float sv = g_exself[r] * g_xl[(size_t)r * 64 + k];
                v = elu1((g_gat[(size_t)r * 64 + k] + sv) * inv + gat_b[k]);
            } else {       // GCN branch finalize: relu(dis*(acc + dis*xg) + b)
                int kk = k - 64;
                float dis = g_dis[r];
                float sv = dis * g_xg[(size_t)r * 64 + kk];
                v = fmaxf(dis * (g_gcn[(size_t)r * 64 + kk] + sv) + gcn_b[kk], 0.f);
            }
        }
        Xs[k][n] = v;
    }
    __syncthreads();
    int ty = tid >> 4, tx = tid & 15;
    int n0 = ty * 4, h0 = tx * 4;
    float acc[4][4] = {};
#pragma unroll 4
    for (int k = 0; k < 128; k++) {
        float4 xv = *(const float4*)&Xs[k][n0];
        float4 wv = *(const float4*)&Ws[k][h0];
        float xs[4] = {xv.x, xv.y, xv.z, xv.w};
        float ws[4] = {wv.x, wv.y, wv.z, wv.w};
#pragma unroll
        for (int i = 0; i < 4; i++)
#pragma unroll
            for (int j = 0; j < 4; j++) acc[i][j] += xs[i] * ws[j];
    }
    float b1v[4], w2v[4];
#pragma unroll
    for (int j = 0; j < 4; j++) { b1v[j] = b1[h0 + j]; w2v[j] = w2[h0 + j]; }
    float part[4];
#pragma unroll
    for (int i = 0; i < 4; i++) {
        float p = 0.f;
#pragma unroll
        for (int j = 0; j < 4; j++) p += fmaxf(acc[i][j] + b1v[j], 0.f) * w2v[j];
        part[i] = p;
    }
#pragma unroll
    for (int off = 8; off >= 1; off >>= 1)
#pragma unroll
        for (int i = 0; i < 4; i++) part[i] += __shfl_down_sync(0xffffffffu, part[i], off);
    if (tx == 0) {
        float bb = b2[0];
#pragma unroll
        for (int i = 0; i < 4; i++) {
            int r = r0 + n0 + i;
            if (r < nrows) out[r] = part[i] + bb;
        }
    }
}

// ---------------- launch ----------------
extern "C" void kernel_launch(void* const* d_in, const int* in_sizes, int n_in,
                              void* d_out, int out_size) {
    const float* x_local  = (const float*)d_in[0];
    const float* x_global = (const float*)d_in[1];
    const float* nf       = (const float*)d_in[2];
    const float* coord    = (const float*)d_in[3];
    const int*   ei       = (const int*)d_in[4];
    const float* fc1w     = (const float*)d_in[5];
    const float* fc1b     = (const float*)d_in[6];
    const float* fc2w     = (const float*)d_in[7];
    const float* fc2b     = (const float*)d_in[8];
    const float* gat_w    = (const float*)d_in[9];
    const float* att_s    = (const float*)d_in[10];
    const float* att_d    = (const float*)d_in[11];
    const float* gat_b    = (const float*)d_in[12];
    const float* gcn_w    = (const float*)d_in[13];
    const float* gcn_b    = (const float*)d_in[14];
    const float* fus_w1   = (const float*)d_in[15];
    const float* fus_b1   = (const float*)d_in[16];
    const float* fus_w2   = (const float*)d_in[17];
    const float* fus_b2   = (const float*)d_in[18];
    float* out = (float*)d_out;

    const int SMEM_G = (128 * 132 + 128 * 68) * (int)sizeof(float);  // 102400
    const int SMEM_F = 2 * 128 * 68 * (int)sizeof(float);            // 69632
    cudaFuncSetAttribute(k_gemm,   cudaFuncAttributeMaxDynamicSharedMemorySize, SMEM_G);
    cudaFuncSetAttribute(k_fusion, cudaFuncAttributeMaxDynamicSharedMemorySize, SMEM_F);

    float *pxl, *pxg, *pgat, *pgcn;
    __half2 *pxlh, *pxgh;
    cudaGetSymbolAddress((void**)&pxl, g_xl);
    cudaGetSymbolAddress((void**)&pxg, g_xg);
    cudaGetSymbolAddress((void**)&pxlh, g_xl_h);
    cudaGetSymbolAddress((void**)&pxgh, g_xg_h);
    cudaGetSymbolAddress((void**)&pgat, g_gat);
    cudaGetSymbolAddress((void**)&pgcn, g_gcn);

    const int NB_N   = (NN + 255) / 256;        // 196
    const int NB_E   = (EE + 255) / 256;        // 6250
    const int NB_E16 = (EE * 16 + 255) / 256;   // 100000
    const int NB_G   = (NN + 127) / 128;        // 391
    const int NB_F   = (NN + 63) / 64;          // 782

    cudaMemsetAsync(pgat, 0, (size_t)NN * 64 * sizeof(float));
    cudaMemsetAsync(pgcn, 0, (size_t)NN * 64 * sizeof(float));
    k_gemm<<<NB_G, 256, SMEM_G>>>(x_local, gat_w, pxl, pxlh, NN);
    k_gemm<<<NB_G, 256, SMEM_G>>>(x_global, gcn_w, pxg, pxgh, NN);
    k_node<<<NB_N, 256>>>(nf, fc1w, fc1b, fc2w, fc2b, att_s, att_d);
    k_edge_scalar<<<NB_E, 256>>>(ei, coord);
    k_dis<<<NB_N, 256>>>();
    k_edge_vec<<<NB_E16, 256>>>(ei);
    k_fusion<<<NB_F, 256, SMEM_F>>>(fus_w1, fus_b1, fus_w2, fus_b2, gat_b, gcn_b, out, NN);
}

// round 4
// speedup vs baseline: 1.3665x; 1.1737x over previous
#include <cuda_runtime.h>
#include <cuda_fp16.h>
#include <math.h>

#define NN 50000
#define EE 1600000
#define RCHUNK 128

// ---------------- scratch ----------------
__device__ __align__(16) float g_xl[NN * 64];
__device__ __align__(16) float g_xg[NN * 64];
__device__ __align__(16) __half2 g_xl_h[NN * 32];
__device__ __align__(16) __half2 g_xg_h[NN * 32];
__device__ __align__(16) float g_gat[NN * 64];
__device__ __align__(16) float g_gcn[NN * 64];
__device__ float g_asrc[NN];
__device__ float g_adst[NN];
__device__ float g_nind[NN];
__device__ float g_exself[NN];
__device__ float g_den[NN];
__device__ float g_deg[NN];
__device__ float g_dis[NN];
__device__ int   g_cnt[NN];
__device__ int   g_start[NN];
__device__ int   g_cursor[NN];
__device__ int   g_bsum[64];
__device__ int   g_boff[64];
__device__ __align__(16) float4 g_edata[EE];   // {src, dst, ex, ew} binned by dst

// ---------------- helpers ----------------
__device__ __forceinline__ void red4(float* p, float a, float b, float c, float d) {
    asm volatile("red.global.add.v4.f32 [%0], {%1,%2,%3,%4};"
                 :: "l"(p), "f"(a), "f"(b), "f"(c), "f"(d) : "memory");
}
__device__ __forceinline__ void red1(float* p, float v) {
    asm volatile("red.global.add.f32 [%0], %1;" :: "l"(p), "f"(v) : "memory");
}
__device__ __forceinline__ float elu1(float v) { return v > 0.f ? v : (expf(v) - 1.f); }

// ---------------- GEMM: out[n][64] = sum_k X[n][k]*W[h][k]  (K=128,H=64) ----------
__global__ void k_gemm(const float* __restrict__ X, const float* __restrict__ W,
                       float* __restrict__ out, __half2* __restrict__ outh, int nrows) {
    extern __shared__ float sm[];
    float (*Xs)[132] = (float(*)[132])sm;
    float (*Ws)[68]  = (float(*)[68])(sm + 128 * 132);
    int tid = threadIdx.x;
    int r0 = blockIdx.x * 128;
    {
        int r = tid & 127, kb = (tid >> 7) * 64;
        int rr = r0 + r;
        const float4* src = (const float4*)(X + (size_t)rr * 128 + kb);
#pragma unroll
        for (int j = 0; j < 16; j++) {
            float4 v = (rr < nrows) ? src[j] : make_float4(0.f, 0.f, 0.f, 0.f);
            int k = kb + 4 * j;
            Xs[k + 0][r] = v.x; Xs[k + 1][r] = v.y;
            Xs[k + 2][r] = v.z; Xs[k + 3][r] = v.w;
        }
    }
    {
        int h = tid & 63, kb = (tid >> 6) * 32;
        const float4* src = (const float4*)(W + (size_t)h * 128 + kb);
#pragma unroll
        for (int j = 0; j < 8; j++) {
            float4 v = src[j];
            int k = kb + 4 * j;
            Ws[k + 0][h] = v.x; Ws[k + 1][h] = v.y;
            Ws[k + 2][h] = v.z; Ws[k + 3][h] = v.w;
        }
    }
    __syncthreads();
    int ty = tid >> 4, tx = tid & 15;
    int n0 = ty * 8, h0 = tx * 4;
    float acc[8][4] = {};
#pragma unroll 4
    for (int k = 0; k < 128; k++) {
        float4 x0 = *(const float4*)&Xs[k][n0];
        float4 x1 = *(const float4*)&Xs[k][n0 + 4];
        float4 wv = *(const float4*)&Ws[k][h0];
        float xs[8] = {x0.x, x0.y, x0.z, x0.w, x1.x, x1.y, x1.z, x1.w};
        float ws[4] = {wv.x, wv.y, wv.z, wv.w};
#pragma unroll
        for (int i = 0; i < 8; i++)
#pragma unroll
            for (int j = 0; j < 4; j++) acc[i][j] += xs[i] * ws[j];
    }
#pragma unroll
    for (int i = 0; i < 8; i++) {
        int r = r0 + n0 + i;
        if (r < nrows) {
            *(float4*)&out[(size_t)r * 64 + h0] =
                make_float4(acc[i][0], acc[i][1], acc[i][2], acc[i][3]);
            outh[(size_t)r * 32 + (h0 >> 1)]     = __floats2half2_rn(acc[i][0], acc[i][1]);
            outh[(size_t)r * 32 + (h0 >> 1) + 1] = __floats2half2_rn(acc[i][2], acc[i][3]);
        }
    }
}

// ---------------- per-node: noise MLP + attention scalars + self-loop init --------
__global__ void k_node(const float* __restrict__ nf, const float* __restrict__ fc1w,
                       const float* __restrict__ fc1b, const float* __restrict__ fc2w,
                       const float* __restrict__ fc2b,
                       const float* __restrict__ att_s, const float* __restrict__ att_d) {
    __shared__ float w1[100], b1[10], w2[10], b2s, ss[64], sd[64];
    int tid = threadIdx.x;
    if (tid < 100) w1[tid] = fc1w[tid];
    if (tid < 10) { b1[tid] = fc1b[tid]; w2[tid] = fc2w[tid]; }
    if (tid == 0) b2s = fc2b[0];
    if (tid >= 128 && tid < 192) ss[tid - 128] = att_s[tid - 128];
    if (tid >= 192) sd[tid - 192] = att_d[tid - 192];
    __syncthreads();
    int i = blockIdx.x * blockDim.x + tid;
    if (i >= NN) return;
    float x[10];
#pragma unroll
    for (int k = 0; k < 10; k++) x[k] = nf[i * 10 + k];
    float acc = b2s;
#pragma unroll
    for (int j = 0; j < 10; j++) {
        float h = b1[j];
#pragma unroll
        for (int k = 0; k < 10; k++) h += x[k] * w1[j * 10 + k];
        acc += elu1(h) * w2[j];
    }
    g_nind[i] = acc;
    const float4* row = (const float4*)(g_xl + (size_t)i * 64);
    float a = 0.f, b = 0.f;
#pragma unroll
    for (int j = 0; j < 16; j++) {
        float4 v = row[j];
        a += v.x * ss[4 * j] + v.y * ss[4 * j + 1] + v.z * ss[4 * j + 2] + v.w * ss[4 * j + 3];
        b += v.x * sd[4 * j] + v.y * sd[4 * j + 1] + v.z * sd[4 * j + 2] + v.w * sd[4 * j + 3];
    }
    g_asrc[i] = a;
    g_adst[i] = b;
    float e = a + b;
    e = e > 0.f ? e : 0.2f * e;
    float ex = expf(e);
    g_exself[i] = ex;
    g_den[i] = ex;
    g_deg[i] = 1.f;
}

// ---------------- histogram over dst ----------------
__global__ void k_hist(const int* __restrict__ ei) {
    int t = blockIdx.x * blockDim.x + threadIdx.x;
    if (t < EE) atomicAdd(&g_cnt[ei[EE + t]], 1);
}

// ---------------- 3-kernel exclusive scan ----------------
__global__ void k_scan1() {
    __shared__ int wsum[8], woff[8];
    int tid = threadIdx.x, lane = tid & 31, wrp = tid >> 5;
    int base = blockIdx.x * 1024 + tid * 4;
    int c0 = 0, c1 = 0, c2 = 0, c3 = 0;
    if (base + 0 < NN) c0 = g_cnt[base + 0];
    if (base + 1 < NN) c1 = g_cnt[base + 1];
    if (base + 2 < NN) c2 = g_cnt[base + 2];
    if (base + 3 < NN) c3 = g_cnt[base + 3];
    int tot = c0 + c1 + c2 + c3;
    int v = tot;
#pragma unroll
    for (int off = 1; off < 32; off <<= 1) {
        int o = __shfl_up_sync(~0u, v, off);
        if (lane >= off) v += o;
    }
    if (lane == 31) wsum[wrp] = v;
    __syncthreads();
    if (wrp == 0 && lane < 8) {
        int w = wsum[lane], iv = w;
#pragma unroll
        for (int off = 1; off < 8; off <<= 1) {
            int o = __shfl_up_sync(0xffu, iv, off);
            if (lane >= off) iv += o;
        }
        woff[lane] = iv - w;
    }
    __syncthreads();
    int excl = (v - tot) + woff[wrp];
    if (base + 0 < NN) g_start[base + 0] = excl;
    if (base + 1 < NN) g_start[base + 1] = excl + c0;
    if (base + 2 < NN) g_start[base + 2] = excl + c0 + c1;
    if (base + 3 < NN) g_start[base + 3] = excl + c0 + c1 + c2;
    if (tid == 255) g_bsum[blockIdx.x] = excl + tot;
}
__global__ void k_scan2(int nblk) {
    int run = 0;
    for (int i = 0; i < nblk; i++) { g_boff[i] = run; run += g_bsum[i]; }
}
__global__ void k_scan3() {
    int i = blockIdx.x * blockDim.x + threadIdx.x;
    if (i >= NN) return;
    int s = g_start[i] + g_boff[i >> 10];
    g_start[i] = s;
    g_cursor[i] = s;
}

// ---------------- edge scalar: ex/ew + deg atomic + binned record write ----------
__global__ void k_edge_scalar(const int* __restrict__ ei, const float* __restrict__ coord) {
    int t = blockIdx.x * blockDim.x + threadIdx.x;
    if (t >= EE) return;
    int s = ei[t], d = ei[EE + t];
    float ni = g_nind[s];
    float2 cs = ((const float2*)coord)[s];
    float2 cd = ((const float2*)coord)[d];
    float dx = cs.x - cd.x, dy = cs.y - cd.y;
    float gw = expf(-(dx * dx + dy * dy) * (1.0f / 1800.0f));
    float z = gw * (1.f + ni) - 1.f;
    float w = 0.1f + 1.9f / (1.f + expf(-z));
    bool m = (w >= 0.2f);
    float e = g_asrc[s] + g_adst[d];
    e = e > 0.f ? e : 0.2f * e;
    float ex = m ? expf(e) : 0.f;
    float ew = m ? w : 0.f;
    if (m) atomicAdd(&g_deg[d], ew);
    int pos = atomicAdd(&g_cursor[d], 1);
    g_edata[pos] = make_float4(__int_as_float(s), __int_as_float(d), ex, ew);
}

// ---------------- dis = rsqrt(deg) ----------------
__global__ void k_dis() {
    int i = blockIdx.x * blockDim.x + threadIdx.x;
    if (i < NN) g_dis[i] = rsqrtf(g_deg[i]);
}

// ---------------- sorted-run reduce: 16 threads/group, 128 records/group ----------
__global__ void k_reduce() {
    int gid = (blockIdx.x * blockDim.x + threadIdx.x) >> 4;
    int l = threadIdx.x & 15;
    int beg = gid * RCHUNK;
    if (beg >= EE) return;
    int end = min(beg + RCHUNK, EE);
    int cur = -1;
    float4 ag = make_float4(0.f, 0.f, 0.f, 0.f);
    float4 ac = make_float4(0.f, 0.f, 0.f, 0.f);
    float den = 0.f;
    for (int i = beg; i < end; i++) {
        float4 rec = __ldg(&g_edata[i]);
        int d = __float_as_int(rec.y);
        if (d != cur) {
            if (cur >= 0) {
                red4(&g_gat[(size_t)cur * 64 + 4 * l], ag.x, ag.y, ag.z, ag.w);
                red4(&g_gcn[(size_t)cur * 64 + 4 * l], ac.x, ac.y, ac.z, ac.w);
                if (l == 0) red1(&g_den[cur], den);
            }
            cur = d;
            ag = make_float4(0.f, 0.f, 0.f, 0.f);
            ac = make_float4(0.f, 0.f, 0.f, 0.f);
            den = 0.f;
        }
        float ex = rec.z, ew = rec.w;
        if (ex != 0.f || ew != 0.f) {
            int s = __float_as_int(rec.x);
            float ewd = ew * __ldg(&g_dis[s]);
            const __half2* pl = &g_xl_h[(size_t)s * 32 + 2 * l];
            float2 f0 = __half22float2(pl[0]), f1 = __half22float2(pl[1]);
            ag.x += ex * f0.x; ag.y += ex * f0.y;
            ag.z += ex * f1.x; ag.w += ex * f1.y;
            const __half2* pg = &g_xg_h[(size_t)s * 32 + 2 * l];
            float2 u0 = __half22float2(pg[0]), u1 = __half22float2(pg[1]);
            ac.x += ewd * u0.x; ac.y += ewd * u0.y;
            ac.z += ewd * u1.x; ac.w += ewd * u1.y;
            den += ex;
        }
    }
    if (cur >= 0) {
        red4(&g_gat[(size_t)cur * 64 + 4 * l], ag.x, ag.y, ag.z, ag.w);
        red4(&g_gcn[(size_t)cur * 64 + 4 * l], ac.x, ac.y, ac.z, ac.w);
        if (l == 0) red1(&g_den[cur], den);
    }
}

// ---------------- fusion: 128-row tile, finalize both branches inline -------------
__global__ void k_fusion(const float* __restrict__ W1, const float* __restrict__ b1,
                         const float* __restrict__ w2, const float* __restrict__ b2,
                         const float* __restrict__ gat_b, const float* __restrict__ gcn_b,
                         float* __restrict__ out, int nrows) {
    extern __shared__ float sm[];
    float (*Xs)[132] = (float(*)[132])sm;
    float (*Ws)[68]  = (float(*)[68])(sm + 128 * 132);
    int tid = threadIdx.x;
    int r0 = blockIdx.x * 128;
    {
        int h = tid & 63, kb = (tid >> 6) * 32;
        const float4* src = (const float4*)(W1 + (size_t)h * 128 + kb);
#pragma unroll
        for (int j = 0; j < 8; j++) {
            float4 v = src[j];
            int k = kb + 4 * j;
            Ws[k + 0][h] = v.x; Ws[k + 1][h] = v.y;
            Ws[k + 2][h] = v.z; Ws[k + 3][h] = v.w;
        }
    }
    {
        int r = tid & 127, half = tid >> 7;  // half 0: GAT feats k=0..63, half 1: GCN k=64..127
        int rr = r0 + r;
        if (rr < nrows) {
            if (half == 0) {
                float inv = 1.f / g_den[rr];
                float exs = g_exself[rr];
                const float4* pa = (const float4*)(g_gat + (size_t)rr * 64);
                const float4* px = (const float4*)(g_xl + (size_t)rr * 64);
                const float4* pb = (const float4*)gat_b;
#pragma unroll
                for (int j = 0; j < 16; j++) {
                    float4 a = pa[j], x = px[j], b = pb[j];
                    int k = 4 * j;
                    Xs[k + 0][r] = elu1((a.x + exs * x.x) * inv + b.x);
                    Xs[k + 1][r] = elu1((a.y + exs * x.y) * inv + b.y);
                    Xs[k + 2][r] = elu1((a.z + exs * x.z) * inv + b.z);
                    Xs[k + 3][r] = elu1((a.w + exs * x.w) * inv + b.w);
                }
            } else {
                float dis = g_dis[rr];
                const float4* pa = (const float4*)(g_gcn + (size_t)rr * 64);
                const float4* px = (const float4*)(g_xg + (size_t)rr * 64);
                const float4* pb = (const float4*)gcn_b;
#pragma unroll
                for (int j = 0; j < 16; j++) {
                    float4 a = pa[j], x = px[j], b = pb[j];
                    int k = 64 + 4 * j;
                    Xs[k + 0][r] = fmaxf(dis * (a.x + dis * x.x) + b.x, 0.f);
                    Xs[k + 1][r] = fmaxf(dis * (a.y + dis * x.y) + b.y, 0.f);
                    Xs[k + 2][r] = fmaxf(dis * (a.z + dis * x.z) + b.z, 0.f);
                    Xs[k + 3][r] = fmaxf(dis * (a.w + dis * x.w) + b.w, 0.f);
                }
            }
        } else {
            int kb = half * 64;
#pragma unroll
            for (int j = 0; j < 64; j++) Xs[kb + j][r] = 0.f;
        }
    }
    __syncthreads();
    int ty = tid >> 4, tx = tid & 15;
    int n0 = ty * 8, h0 = tx * 4;
    float acc[8][4] = {};
#pragma unroll 4
    for (int k = 0; k < 128; k++) {
        float4 x0 = *(const float4*)&Xs[k][n0];
        float4 x1 = *(const float4*)&Xs[k][n0 + 4];
        float4 wv = *(const float4*)&Ws[k][h0];
        float xs[8] = {x0.x, x0.y, x0.z, x0.w, x1.x, x1.y, x1.z, x1.w};
        float ws[4] = {wv.x, wv.y, wv.z, wv.w};
#pragma unroll
        for (int i = 0; i < 8; i++)
#pragma unroll
            for (int j = 0; j < 4; j++) acc[i][j] += xs[i] * ws[j];
    }
    float b1v[4], w2v[4];
#pragma unroll
    for (int j = 0; j < 4; j++) { b1v[j] = b1[h0 + j]; w2v[j] = w2[h0 + j]; }
    float part[8];
#pragma unroll
    for (int i = 0; i < 8; i++) {
        float p = 0.f;
#pragma unroll
        for (int j = 0; j < 4; j++) p += fmaxf(acc[i][j] + b1v[j], 0.f) * w2v[j];
        part[i] = p;
    }
#pragma unroll
    for (int off = 8; off >= 1; off >>= 1)
#pragma unroll
        for (int i = 0; i < 8; i++) part[i] += __shfl_down_sync(0xffffffffu, part[i], off);
    if (tx == 0) {
        float bb = b2[0];
#pragma unroll
        for (int i = 0; i < 8; i++) {
            int r = r0 + n0 + i;
            if (r < nrows) out[r] = part[i] + bb;
        }
    }
}

// ---------------- launch ----------------
extern "C" void kernel_launch(void* const* d_in, const int* in_sizes, int n_in,
                              void* d_out, int out_size) {
    const float* x_local  = (const float*)d_in[0];
    const float* x_global = (const float*)d_in[1];
    const float* nf       = (const float*)d_in[2];
    const float* coord    = (const float*)d_in[3];
    const int*   ei       = (const int*)d_in[4];
    const float* fc1w     = (const float*)d_in[5];
    const float* fc1b     = (const float*)d_in[6];
    const float* fc2w     = (const float*)d_in[7];
    const float* fc2b     = (const float*)d_in[8];
    const float* gat_w    = (const float*)d_in[9];
    const float* att_s    = (const float*)d_in[10];
    const float* att_d    = (const float*)d_in[11];
    const float* gat_b    = (const float*)d_in[12];
    const float* gcn_w    = (const float*)d_in[13];
    const float* gcn_b    = (const float*)d_in[14];
    const float* fus_w1   = (const float*)d_in[15];
    const float* fus_b1   = (const float*)d_in[16];
    const float* fus_w2   = (const float*)d_in[17];
    const float* fus_b2   = (const float*)d_in[18];
    float* out = (float*)d_out;

    const int SMEM_G = (128 * 132 + 128 * 68) * (int)sizeof(float);  // 102400
    cudaFuncSetAttribute(k_gemm,   cudaFuncAttributeMaxDynamicSharedMemorySize, SMEM_G);
    cudaFuncSetAttribute(k_fusion, cudaFuncAttributeMaxDynamicSharedMemorySize, SMEM_G);

    float *pxl, *pxg, *pgat, *pgcn;
    __half2 *pxlh, *pxgh;
    void *pcnt;
    cudaGetSymbolAddress((void**)&pxl, g_xl);
    cudaGetSymbolAddress((void**)&pxg, g_xg);
    cudaGetSymbolAddress((void**)&pxlh, g_xl_h);
    cudaGetSymbolAddress((void**)&pxgh, g_xg_h);
    cudaGetSymbolAddress((void**)&pgat, g_gat);
    cudaGetSymbolAddress((void**)&pgcn, g_gcn);
    cudaGetSymbolAddress(&pcnt, g_cnt);

    const int NB_N   = (NN + 255) / 256;                 // 196
    const int NB_E   = (EE + 255) / 256;                 // 6250
    const int NB_G   = (NN + 127) / 128;                 // 391
    const int NSCAN  = (NN + 1023) / 1024;               // 49
    const int NGROUP = (EE + RCHUNK - 1) / RCHUNK;       // 12500
    const int NB_R   = (NGROUP * 16 + 255) / 256;        // 782

    cudaMemsetAsync(pcnt, 0, NN * sizeof(int));
    cudaMemsetAsync(pgat, 0, (size_t)NN * 64 * sizeof(float));
    cudaMemsetAsync(pgcn, 0, (size_t)NN * 64 * sizeof(float));
    k_hist<<<NB_E, 256>>>(ei);
    k_gemm<<<NB_G, 256, SMEM_G>>>(x_local, gat_w, pxl, pxlh, NN);
    k_gemm<<<NB_G, 256, SMEM_G>>>(x_global, gcn_w, pxg, pxgh, NN);
    k_node<<<NB_N, 256>>>(nf, fc1w, fc1b, fc2w, fc2b, att_s, att_d);
    k_scan1<<<NSCAN, 256>>>();
    k_scan2<<<1, 1>>>(NSCAN);
    k_scan3<<<NB_N, 256>>>();
    k_edge_scalar<<<NB_E, 256>>>(ei, coord);
    k_dis<<<NB_N, 256>>>();
    k_reduce<<<NB_R, 256>>>();
    k_fusion<<<NB_G, 256, SMEM_G>>>(fus_w1, fus_b1, fus_w2, fus_b2, gat_b, gcn_b, out, NN);
}

// round 5
// speedup vs baseline: 1.4620x; 1.0699x over previous
#include <cuda_runtime.h>
#include <cuda_fp16.h>
#include <math.h>

#define NN 50000
#define EE 1600000
#define RCHUNK 64

// ---------------- scratch ----------------
__device__ __align__(16) float g_xl[NN * 64];
__device__ __align__(16) float g_xg[NN * 64];
__device__ __align__(16) __half2 g_xl_h[NN * 32];
__device__ __align__(16) __half2 g_xg_h[NN * 32];
__device__ __align__(16) float g_gat[NN * 64];
__device__ __align__(16) float g_gcn[NN * 64];
__device__ __align__(16) float g_node4[NN * 4];   // {cx, cy, nind, asrc}
__device__ __align__(16) float g_nodeD[NN * 4];   // {cx, cy, adst, 0}
__device__ float g_exself[NN];
__device__ float g_den[NN];
__device__ float g_deg[NN];
__device__ float g_dis[NN];
__device__ int   g_cnt[NN];
__device__ int   g_startx[NN + 1];   // bin starts + sentinel EE
__device__ int   g_cursor[NN];
__device__ int   g_bsum[64];
__device__ int   g_boff[64];
__device__ __align__(8) uint2 g_edata8[EE];  // {src, half2(ex,ew)} binned by dst

// ---------------- helpers ----------------
__device__ __forceinline__ void red4(float* p, float a, float b, float c, float d) {
    asm volatile("red.global.add.v4.f32 [%0], {%1,%2,%3,%4};"
                 :: "l"(p), "f"(a), "f"(b), "f"(c), "f"(d) : "memory");
}
__device__ __forceinline__ void red1(float* p, float v) {
    asm volatile("red.global.add.f32 [%0], %1;" :: "l"(p), "f"(v) : "memory");
}
__device__ __forceinline__ float elu1(float v) { return v > 0.f ? v : (expf(v) - 1.f); }

// ---------------- GEMM + optional attention epilogue ----------------
// 128 rows/block, 256 threads, 8x4 tile. If att_s != null, computes per-row
// attention scalars and the self-loop init (asrc->node4.w, adst->nodeD.z,
// exself/den/deg).
__global__ void k_gemm(const float* __restrict__ X, const float* __restrict__ W,
                       float* __restrict__ out, __half2* __restrict__ outh,
                       const float* __restrict__ att_s, const float* __restrict__ att_d,
                       int nrows) {
    extern __shared__ float sm[];
    float (*Xs)[132] = (float(*)[132])sm;
    float (*Ws)[68]  = (float(*)[68])(sm + 128 * 132);
    __shared__ float s_as[64], s_ad[64];
    int tid = threadIdx.x;
    int r0 = blockIdx.x * 128;
    if (att_s) {
        if (tid < 64) s_as[tid] = att_s[tid];
        else if (tid < 128) s_ad[tid - 64] = att_d[tid - 64];
    }
    {
        int r = tid & 127, kb = (tid >> 7) * 64;
        int rr = r0 + r;
        const float4* src = (const float4*)(X + (size_t)rr * 128 + kb);
#pragma unroll
        for (int j = 0; j < 16; j++) {
            float4 v = (rr < nrows) ? src[j] : make_float4(0.f, 0.f, 0.f, 0.f);
            int k = kb + 4 * j;
            Xs[k + 0][r] = v.x; Xs[k + 1][r] = v.y;
            Xs[k + 2][r] = v.z; Xs[k + 3][r] = v.w;
        }
    }
    {
        int h = tid & 63, kb = (tid >> 6) * 32;
        const float4* src = (const float4*)(W + (size_t)h * 128 + kb);
#pragma unroll
        for (int j = 0; j < 8; j++) {
            float4 v = src[j];
            int k = kb + 4 * j;
            Ws[k + 0][h] = v.x; Ws[k + 1][h] = v.y;
            Ws[k + 2][h] = v.z; Ws[k + 3][h] = v.w;
        }
    }
    __syncthreads();
    int ty = tid >> 4, tx = tid & 15;
    int n0 = ty * 8, h0 = tx * 4;
    float acc[8][4] = {};
#pragma unroll 4
    for (int k = 0; k < 128; k++) {
        float4 x0 = *(const float4*)&Xs[k][n0];
        float4 x1 = *(const float4*)&Xs[k][n0 + 4];
        float4 wv = *(const float4*)&Ws[k][h0];
        float xs[8] = {x0.x, x0.y, x0.z, x0.w, x1.x, x1.y, x1.z, x1.w};
        float ws[4] = {wv.x, wv.y, wv.z, wv.w};
#pragma unroll
        for (int i = 0; i < 8; i++)
#pragma unroll
            for (int j = 0; j < 4; j++) acc[i][j] += xs[i] * ws[j];
    }
#pragma unroll
    for (int i = 0; i < 8; i++) {
        int r = r0 + n0 + i;
        if (r < nrows) {
            *(float4*)&out[(size_t)r * 64 + h0] =
                make_float4(acc[i][0], acc[i][1], acc[i][2], acc[i][3]);
            outh[(size_t)r * 32 + (h0 >> 1)]     = __floats2half2_rn(acc[i][0], acc[i][1]);
            outh[(size_t)r * 32 + (h0 >> 1) + 1] = __floats2half2_rn(acc[i][2], acc[i][3]);
        }
    }
    if (att_s) {
        float ap[8], bp[8];
#pragma unroll
        for (int i = 0; i < 8; i++) {
            ap[i] = acc[i][0] * s_as[h0] + acc[i][1] * s_as[h0 + 1]
                  + acc[i][2] * s_as[h0 + 2] + acc[i][3] * s_as[h0 + 3];
            bp[i] = acc[i][0] * s_ad[h0] + acc[i][1] * s_ad[h0 + 1]
                  + acc[i][2] * s_ad[h0 + 2] + acc[i][3] * s_ad[h0 + 3];
        }
#pragma unroll
        for (int off = 8; off >= 1; off >>= 1)
#pragma unroll
            for (int i = 0; i < 8; i++) {
                ap[i] += __shfl_down_sync(0xffffffffu, ap[i], off, 16);
                bp[i] += __shfl_down_sync(0xffffffffu, bp[i], off, 16);
            }
        if (tx == 0) {
#pragma unroll
            for (int i = 0; i < 8; i++) {
                int r = r0 + n0 + i;
                if (r < nrows) {
                    g_node4[4 * r + 3] = ap[i];
                    g_nodeD[4 * r + 2] = bp[i];
                    float e = ap[i] + bp[i];
                    e = e > 0.f ? e : 0.2f * e;
                    float ex = expf(e);
                    g_exself[r] = ex;
                    g_den[r] = ex;
                    g_deg[r] = 1.f;
                }
            }
        }
    }
}

// ---------------- per-node noise MLP + coord packing ----------------
__global__ void k_nind(const float* __restrict__ nf, const float* __restrict__ coord,
                       const float* __restrict__ fc1w, const float* __restrict__ fc1b,
                       const float* __restrict__ fc2w, const float* __restrict__ fc2b) {
    __shared__ float w1[100], b1[10], w2[10], b2s;
    int tid = threadIdx.x;
    if (tid < 100) w1[tid] = fc1w[tid];
    if (tid < 10) { b1[tid] = fc1b[tid]; w2[tid] = fc2w[tid]; }
    if (tid == 0) b2s = fc2b[0];
    __syncthreads();
    int i = blockIdx.x * blockDim.x + tid;
    if (i >= NN) return;
    float x[10];
#pragma unroll
    for (int k = 0; k < 10; k++) x[k] = nf[i * 10 + k];
    float acc = b2s;
#pragma unroll
    for (int j = 0; j < 10; j++) {
        float h = b1[j];
#pragma unroll
        for (int k = 0; k < 10; k++) h += x[k] * w1[j * 10 + k];
        acc += elu1(h) * w2[j];
    }
    float2 c = ((const float2*)coord)[i];
    *(float4*)&g_node4[4 * i] = make_float4(c.x, c.y, acc, 0.f);  // .w by epilogue
    *(float4*)&g_nodeD[4 * i] = make_float4(c.x, c.y, 0.f, 0.f);  // .z by epilogue
}

// ---------------- histogram over dst ----------------
__global__ void k_hist(const int* __restrict__ ei) {
    int t = blockIdx.x * blockDim.x + threadIdx.x;
    if (t < EE) atomicAdd(&g_cnt[ei[EE + t]], 1);
}

// ---------------- 3-kernel exclusive scan -> g_startx, g_cursor ----------------
__global__ void k_scan1() {
    __shared__ int wsum[8], woff[8];
    int tid = threadIdx.x, lane = tid & 31, wrp = tid >> 5;
    int base = blockIdx.x * 1024 + tid * 4;
    int c0 = 0, c1 = 0, c2 = 0, c3 = 0;
    if (base + 0 < NN) c0 = g_cnt[base + 0];
    if (base + 1 < NN) c1 = g_cnt[base + 1];
    if (base + 2 < NN) c2 = g_cnt[base + 2];
    if (base + 3 < NN) c3 = g_cnt[base + 3];
    int tot = c0 + c1 + c2 + c3;
    int v = tot;
#pragma unroll
    for (int off = 1; off < 32; off <<= 1) {
        int o = __shfl_up_sync(~0u, v, off);
        if (lane >= off) v += o;
    }
    if (lane == 31) wsum[wrp] = v;
    __syncthreads();
    if (wrp == 0 && lane < 8) {
        int w = wsum[lane], iv = w;
#pragma unroll
        for (int off = 1; off < 8; off <<= 1) {
            int o = __shfl_up_sync(0xffu, iv, off);
            if (lane >= off) iv += o;
        }
        woff[lane] = iv - w;
    }
    __syncthreads();
    int excl = (v - tot) + woff[wrp];
    if (base + 0 < NN) g_startx[base + 0] = excl;
    if (base + 1 < NN) g_startx[base + 1] = excl + c0;
    if (base + 2 < NN) g_startx[base + 2] = excl + c0 + c1;
    if (base + 3 < NN) g_startx[base + 3] = excl + c0 + c1 + c2;
    if (tid == 255) g_bsum[blockIdx.x] = excl + tot;
}
__global__ void k_scan2(int nblk) {
    int run = 0;
    for (int i = 0; i < nblk; i++) { g_boff[i] = run; run += g_bsum[i]; }
    g_startx[NN] = EE;
}
__global__ void k_scan3() {
    int i = blockIdx.x * blockDim.x + threadIdx.x;
    if (i >= NN) return;
    int s = g_startx[i] + g_boff[i >> 10];
    g_startx[i] = s;
    g_cursor[i] = s;
}

// ---------------- bin pass: ex/ew + deg atomic + 8B record write ----------------
__global__ void k_bin(const int* __restrict__ ei) {
    int t = blockIdx.x * blockDim.x + threadIdx.x;
    if (t >= EE) return;
    int s = ei[t], d = ei[EE + t];
    float4 ns = *(const float4*)&g_node4[4 * s];  // cx, cy, nind, asrc
    float4 nd = *(const float4*)&g_nodeD[4 * d];  // cx, cy, adst
    float dx = ns.x - nd.x, dy = ns.y - nd.y;
    float gw = expf(-(dx * dx + dy * dy) * (1.0f / 1800.0f));
    float z = gw * (1.f + ns.z) - 1.f;
    float w = 0.1f + 1.9f / (1.f + expf(-z));
    bool m = (w >= 0.2f);
    float e = ns.w + nd.z;
    e = e > 0.f ? e : 0.2f * e;
    float ex = expf(e);
    __half2 p = m ? __floats2half2_rn(ex, w) : __floats2half2_rn(0.f, 0.f);
    if (m) atomicAdd(&g_deg[d], w);
    int pos = atomicAdd(&g_cursor[d], 1);
    unsigned int pb = *reinterpret_cast<unsigned int*>(&p);
    g_edata8[pos] = make_uint2((unsigned int)s, pb);
}

// ---------------- dis = rsqrt(deg) ----------------
__global__ void k_dis() {
    int i = blockIdx.x * blockDim.x + threadIdx.x;
    if (i < NN) g_dis[i] = rsqrtf(g_deg[i]);
}

// ---------------- sorted-run reduce: 16 threads/group, 64 records/group --------
__global__ void k_reduce() {
    int gid = (blockIdx.x * blockDim.x + threadIdx.x) >> 4;
    int l = threadIdx.x & 15;
    int beg = gid * RCHUNK;
    if (beg >= EE) return;
    int end = min(beg + RCHUNK, EE);
    // binary search: largest n with startx[n] <= beg
    int lo = 0, hi = NN - 1;
    while (lo < hi) {
        int mid = (lo + hi + 1) >> 1;
        if (g_startx[mid] <= beg) lo = mid; else hi = mid - 1;
    }
    int n = lo;
    int nxt = g_startx[n + 1];
    float4 ag = make_float4(0.f, 0.f, 0.f, 0.f);
    float4 ac = make_float4(0.f, 0.f, 0.f, 0.f);
    float den = 0.f;
    bool dirty = false;
    uint2 rec = g_edata8[beg];
    for (int i = beg; i < end; i++) {
        uint2 cur = rec;
        if (i + 1 < end) rec = g_edata8[i + 1];
        while (i >= nxt) {
            if (dirty) {
                red4(&g_gat[(size_t)n * 64 + 4 * l], ag.x, ag.y, ag.z, ag.w);
                red4(&g_gcn[(size_t)n * 64 + 4 * l], ac.x, ac.y, ac.z, ac.w);
                if (l == 0) red1(&g_den[n], den);
                ag = make_float4(0.f, 0.f, 0.f, 0.f);
                ac = make_float4(0.f, 0.f, 0.f, 0.f);
                den = 0.f;
                dirty = false;
            }
            n++;
            nxt = g_startx[n + 1];
        }
        __half2 p; *reinterpret_cast<unsigned int*>(&p) = cur.y;
        float2 exw = __half22float2(p);
        if (exw.x == 0.f && exw.y == 0.f) continue;  // masked edge
        int s = (int)cur.x;
        float diss = __ldg(&g_dis[s]);
        float ewd = exw.y * diss;
        const __half2* pl = &g_xl_h[(size_t)s * 32 + 2 * l];
        float2 f0 = __half22float2(pl[0]), f1 = __half22float2(pl[1]);
        ag.x += exw.x * f0.x; ag.y += exw.x * f0.y;
        ag.z += exw.x * f1.x; ag.w += exw.x * f1.y;
        const __half2* pg = &g_xg_h[(size_t)s * 32 + 2 * l];
        float2 u0 = __half22float2(pg[0]), u1 = __half22float2(pg[1]);
        ac.x += ewd * u0.x; ac.y += ewd * u0.y;
        ac.z += ewd * u1.x; ac.w += ewd * u1.y;
        den += exw.x;
        dirty = true;
    }
    if (dirty) {
        red4(&g_gat[(size_t)n * 64 + 4 * l], ag.x, ag.y, ag.z, ag.w);
        red4(&g_gcn[(size_t)n * 64 + 4 * l], ac.x, ac.y, ac.z, ac.w);
        if (l == 0) red1(&g_den[n], den);
    }
}

// ---------------- fusion: 128-row tile, finalize both branches inline -----------
__global__ void k_fusion(const float* __restrict__ W1, const float* __restrict__ b1,
                         const float* __restrict__ w2, const float* __restrict__ b2,
                         const float* __restrict__ gat_b, const float* __restrict__ gcn_b,
                         float* __restrict__ out, int nrows) {
    extern __shared__ float sm[];
    float (*Xs)[132] = (float(*)[132])sm;
    float (*Ws)[68]  = (float(*)[68])(sm + 128 * 132);
    int tid = threadIdx.x;
    int r0 = blockIdx.x * 128;
    {
        int h = tid & 63, kb = (tid >> 6) * 32;
        const float4* src = (const float4*)(W1 + (size_t)h * 128 + kb);
#pragma unroll
        for (int j = 0; j < 8; j++) {
            float4 v = src[j];
            int k = kb + 4 * j;
            Ws[k + 0][h] = v.x; Ws[k + 1][h] = v.y;
            Ws[k + 2][h] = v.z; Ws[k + 3][h] = v.w;
        }
    }
    {
        int r = tid & 127, half = tid >> 7;
        int rr = r0 + r;
        if (rr < nrows) {
            if (half == 0) {
                float inv = 1.f / g_den[rr];
                float exs = g_exself[rr];
                const float4* pa = (const float4*)(g_gat + (size_t)rr * 64);
                const float4* px = (const float4*)(g_xl + (size_t)rr * 64);
                const float4* pb = (const float4*)gat_b;
#pragma unroll
                for (int j = 0; j < 16; j++) {
                    float4 a = pa[j], x = px[j], b = pb[j];
                    int k = 4 * j;
                    Xs[k + 0][r] = elu1((a.x + exs * x.x) * inv + b.x);
                    Xs[k + 1][r] = elu1((a.y + exs * x.y) * inv + b.y);
                    Xs[k + 2][r] = elu1((a.z + exs * x.z) * inv + b.z);
                    Xs[k + 3][r] = elu1((a.w + exs * x.w) * inv + b.w);
                }
            } else {
                float dis = g_dis[rr];
                const float4* pa = (const float4*)(g_gcn + (size_t)rr * 64);
                const float4* px = (const float4*)(g_xg + (size_t)rr * 64);
                const float4* pb = (const float4*)gcn_b;
#pragma unroll
                for (int j = 0; j < 16; j++) {
                    float4 a = pa[j], x = px[j], b = pb[j];
                    int k = 64 + 4 * j;
                    Xs[k + 0][r] = fmaxf(dis * (a.x + dis * x.x) + b.x, 0.f);
                    Xs[k + 1][r] = fmaxf(dis * (a.y + dis * x.y) + b.y, 0.f);
                    Xs[k + 2][r] = fmaxf(dis * (a.z + dis * x.z) + b.z, 0.f);
                    Xs[k + 3][r] = fmaxf(dis * (a.w + dis * x.w) + b.w, 0.f);
                }
            }
        } else {
            int kb = half * 64;
#pragma unroll
            for (int j = 0; j < 64; j++) Xs[kb + j][r] = 0.f;
        }
    }
    __syncthreads();
    int ty = tid >> 4, tx = tid & 15;
    int n0 = ty * 8, h0 = tx * 4;
    float acc[8][4] = {};
#pragma unroll 4
    for (int k = 0; k < 128; k++) {
        float4 x0 = *(const float4*)&Xs[k][n0];
        float4 x1 = *(const float4*)&Xs[k][n0 + 4];
        float4 wv = *(const float4*)&Ws[k][h0];
        float xs[8] = {x0.x, x0.y, x0.z, x0.w, x1.x, x1.y, x1.z, x1.w};
        float ws[4] = {wv.x, wv.y, wv.z, wv.w};
#pragma unroll
        for (int i = 0; i < 8; i++)
#pragma unroll
            for (int j = 0; j < 4; j++) acc[i][j] += xs[i] * ws[j];
    }
    float b1v[4], w2v[4];
#pragma unroll
    for (int j = 0; j < 4; j++) { b1v[j] = b1[h0 + j]; w2v[j] = w2[h0 + j]; }
    float part[8];
#pragma unroll
    for (int i = 0; i < 8; i++) {
        float p = 0.f;
#pragma unroll
        for (int j = 0; j < 4; j++) p += fmaxf(acc[i][j] + b1v[j], 0.f) * w2v[j];
        part[i] = p;
    }
#pragma unroll
    for (int off = 8; off >= 1; off >>= 1)
#pragma unroll
        for (int i = 0; i < 8; i++) part[i] += __shfl_down_sync(0xffffffffu, part[i], off, 16);
    if (tx == 0) {
        float bb = b2[0];
#pragma unroll
        for (int i = 0; i < 8; i++) {
            int r = r0 + n0 + i;
            if (r < nrows) out[r] = part[i] + bb;
        }
    }
}

// ---------------- launch ----------------
extern "C" void kernel_launch(void* const* d_in, const int* in_sizes, int n_in,
                              void* d_out, int out_size) {
    const float* x_local  = (const float*)d_in[0];
    const float* x_global = (const float*)d_in[1];
    const float* nf       = (const float*)d_in[2];
    const float* coord    = (const float*)d_in[3];
    const int*   ei       = (const int*)d_in[4];
    const float* fc1w     = (const float*)d_in[5];
    const float* fc1b     = (const float*)d_in[6];
    const float* fc2w     = (const float*)d_in[7];
    const float* fc2b     = (const float*)d_in[8];
    const float* gat_w    = (const float*)d_in[9];
    const float* att_s    = (const float*)d_in[10];
    const float* att_d    = (const float*)d_in[11];
    const float* gat_b    = (const float*)d_in[12];
    const float* gcn_w    = (const float*)d_in[13];
    const float* gcn_b    = (const float*)d_in[14];
    const float* fus_w1   = (const float*)d_in[15];
    const float* fus_b1   = (const float*)d_in[16];
    const float* fus_w2   = (const float*)d_in[17];
    const float* fus_b2   = (const float*)d_in[18];
    float* out = (float*)d_out;

    const int SMEM_G = (128 * 132 + 128 * 68) * (int)sizeof(float);  // 102400
    cudaFuncSetAttribute(k_gemm,   cudaFuncAttributeMaxDynamicSharedMemorySize, SMEM_G);
    cudaFuncSetAttribute(k_fusion, cudaFuncAttributeMaxDynamicSharedMemorySize, SMEM_G);

    float *pxl, *pxg, *pgat, *pgcn;
    __half2 *pxlh, *pxgh;
    void *pcnt;
    cudaGetSymbolAddress((void**)&pxl, g_xl);
    cudaGetSymbolAddress((void**)&pxg, g_xg);
    cudaGetSymbolAddress((void**)&pxlh, g_xl_h);
    cudaGetSymbolAddress((void**)&pxgh, g_xg_h);
    cudaGetSymbolAddress((void**)&pgat, g_gat);
    cudaGetSymbolAddress((void**)&pgcn, g_gcn);
    cudaGetSymbolAddress(&pcnt, g_cnt);

    const int NB_N   = (NN + 255) / 256;                 // 196
    const int NB_E   = (EE + 255) / 256;                 // 6250
    const int NB_G   = (NN + 127) / 128;                 // 391
    const int NSCAN  = (NN + 1023) / 1024;               // 49
    const int NGROUP = (EE + RCHUNK - 1) / RCHUNK;       // 25000
    const int NB_R   = (NGROUP * 16 + 255) / 256;        // 1563

    cudaMemsetAsync(pcnt, 0, NN * sizeof(int));
    cudaMemsetAsync(pgat, 0, (size_t)NN * 64 * sizeof(float));
    cudaMemsetAsync(pgcn, 0, (size_t)NN * 64 * sizeof(float));
    k_hist<<<NB_E, 256>>>(ei);
    k_nind<<<NB_N, 256>>>(nf, coord, fc1w, fc1b, fc2w, fc2b);
    k_gemm<<<NB_G, 256, SMEM_G>>>(x_local, gat_w, pxl, pxlh, att_s, att_d, NN);
    k_gemm<<<NB_G, 256, SMEM_G>>>(x_global, gcn_w, pxg, pxgh, nullptr, nullptr, NN);
    k_scan1<<<NSCAN, 256>>>();
    k_scan2<<<1, 1>>>(NSCAN);
    k_scan3<<<NB_N, 256>>>();
    k_bin<<<NB_E, 256>>>(ei);
    k_dis<<<NB_N, 256>>>();
    k_reduce<<<NB_R, 256>>>();
    k_fusion<<<NB_G, 256, SMEM_G>>>(fus_w1, fus_b1, fus_w2, fus_b2, gat_b, gcn_b, out, NN);
}

// round 6
// speedup vs baseline: 1.5643x; 1.0700x over previous
#include <cuda_runtime.h>
#include <cuda_fp16.h>
#include <math.h>

#define NN 50000
#define EE 1600000
#define RCHUNK 64

// ---------------- scratch ----------------
__device__ __align__(16) __half2 g_xl_h[NN * 32];  // x_local @ gat_w^T (fp16)
__device__ __align__(16) __half2 g_xg_h[NN * 32];  // x_global @ gcn_w^T (fp16)
__device__ __align__(16) float g_gat[NN * 64];
__device__ __align__(16) float g_gcn[NN * 64];
__device__ __align__(16) float g_node4[NN * 4];    // {cx, cy, nind, asrc}
__device__ __align__(16) float g_nodeD[NN * 4];    // {cx, cy, adst, 0}
__device__ float g_exself[NN];
__device__ float g_den[NN];
__device__ float g_deg[NN];
__device__ float g_dis[NN];
__device__ int   g_cnt[NN];
__device__ int   g_startx[NN + 1];
__device__ int   g_cursor[NN];
__device__ int   g_bsum[64];
__device__ int   g_boff[64];
__device__ __align__(8) uint2 g_edata8[EE];  // {src, half2(ex,ew)} binned by dst

// ---------------- helpers ----------------
__device__ __forceinline__ void red4(float* p, float a, float b, float c, float d) {
    asm volatile("red.global.add.v4.f32 [%0], {%1,%2,%3,%4};"
                 :: "l"(p), "f"(a), "f"(b), "f"(c), "f"(d) : "memory");
}
__device__ __forceinline__ void red1(float* p, float v) {
    asm volatile("red.global.add.f32 [%0], %1;" :: "l"(p), "f"(v) : "memory");
}
__device__ __forceinline__ float elu1(float v) { return v > 0.f ? v : (expf(v) - 1.f); }

// ---------------- GEMM (K-split x2) + optional attention epilogue ----------------
// 128 rows/block, 256 threads, 8x4 tile. smem 51200 B -> 4 CTAs/SM.
__global__ void __launch_bounds__(256, 4)
k_gemm(const float* __restrict__ X, const float* __restrict__ W,
       __half2* __restrict__ outh,
       const float* __restrict__ att_s, const float* __restrict__ att_d, int nrows) {
    extern __shared__ float sm[];
    float (*Xs)[132] = (float(*)[132])sm;               // [64 k][128 n]
    float (*Ws)[68]  = (float(*)[68])(sm + 64 * 132);   // [64 k][64 h]
    __shared__ float s_as[64], s_ad[64];
    int tid = threadIdx.x;
    int r0 = blockIdx.x * 128;
    if (att_s) {
        if (tid < 64) s_as[tid] = att_s[tid];
        else if (tid < 128) s_ad[tid - 64] = att_d[tid - 64];
    }
    int ty = tid >> 4, tx = tid & 15;
    int n0 = ty * 8, h0 = tx * 4;
    float acc[8][4] = {};

#pragma unroll
    for (int p = 0; p < 2; p++) {
        if (p) __syncthreads();
        {
            int r = tid & 127, ko = (tid >> 7) * 32;
            int rr = r0 + r;
            const float4* src = (const float4*)(X + (size_t)rr * 128 + p * 64 + ko);
#pragma unroll
            for (int j = 0; j < 8; j++) {
                float4 v = (rr < nrows) ? src[j] : make_float4(0.f, 0.f, 0.f, 0.f);
                int k = ko + 4 * j;
                Xs[k + 0][r] = v.x; Xs[k + 1][r] = v.y;
                Xs[k + 2][r] = v.z; Xs[k + 3][r] = v.w;
            }
        }
        {
            int h = tid & 63, kq = (tid >> 6) * 16;
            const float4* src = (const float4*)(W + (size_t)h * 128 + p * 64 + kq);
#pragma unroll
            for (int j = 0; j < 4; j++) {
                float4 v = src[j];
                int k = kq + 4 * j;
                Ws[k + 0][h] = v.x; Ws[k + 1][h] = v.y;
                Ws[k + 2][h] = v.z; Ws[k + 3][h] = v.w;
            }
        }
        __syncthreads();
#pragma unroll 4
        for (int k = 0; k < 64; k++) {
            float4 x0 = *(const float4*)&Xs[k][n0];
            float4 x1 = *(const float4*)&Xs[k][n0 + 4];
            float4 wv = *(const float4*)&Ws[k][h0];
            float xs[8] = {x0.x, x0.y, x0.z, x0.w, x1.x, x1.y, x1.z, x1.w};
            float ws[4] = {wv.x, wv.y, wv.z, wv.w};
#pragma unroll
            for (int i = 0; i < 8; i++)
#pragma unroll
                for (int j = 0; j < 4; j++) acc[i][j] += xs[i] * ws[j];
        }
    }

#pragma unroll
    for (int i = 0; i < 8; i++) {
        int r = r0 + n0 + i;
        if (r < nrows) {
            outh[(size_t)r * 32 + (h0 >> 1)]     = __floats2half2_rn(acc[i][0], acc[i][1]);
            outh[(size_t)r * 32 + (h0 >> 1) + 1] = __floats2half2_rn(acc[i][2], acc[i][3]);
        }
    }
    if (att_s) {
        float ap[8], bp[8];
#pragma unroll
        for (int i = 0; i < 8; i++) {
            ap[i] = acc[i][0] * s_as[h0] + acc[i][1] * s_as[h0 + 1]
                  + acc[i][2] * s_as[h0 + 2] + acc[i][3] * s_as[h0 + 3];
            bp[i] = acc[i][0] * s_ad[h0] + acc[i][1] * s_ad[h0 + 1]
                  + acc[i][2] * s_ad[h0 + 2] + acc[i][3] * s_ad[h0 + 3];
        }
#pragma unroll
        for (int off = 8; off >= 1; off >>= 1)
#pragma unroll
            for (int i = 0; i < 8; i++) {
                ap[i] += __shfl_down_sync(0xffffffffu, ap[i], off, 16);
                bp[i] += __shfl_down_sync(0xffffffffu, bp[i], off, 16);
            }
        if (tx == 0) {
#pragma unroll
            for (int i = 0; i < 8; i++) {
                int r = r0 + n0 + i;
                if (r < nrows) {
                    g_node4[4 * r + 3] = ap[i];
                    g_nodeD[4 * r + 2] = bp[i];
                    float e = ap[i] + bp[i];
                    e = e > 0.f ? e : 0.2f * e;
                    float ex = expf(e);
                    g_exself[r] = ex;
                    g_den[r] = ex;
                    g_deg[r] = 1.f;
                }
            }
        }
    }
}

// ---------------- per-node noise MLP + coord packing ----------------
__global__ void k_nind(const float* __restrict__ nf, const float* __restrict__ coord,
                       const float* __restrict__ fc1w, const float* __restrict__ fc1b,
                       const float* __restrict__ fc2w, const float* __restrict__ fc2b) {
    __shared__ float w1[100], b1[10], w2[10], b2s;
    int tid = threadIdx.x;
    if (tid < 100) w1[tid] = fc1w[tid];
    if (tid < 10) { b1[tid] = fc1b[tid]; w2[tid] = fc2w[tid]; }
    if (tid == 0) b2s = fc2b[0];
    __syncthreads();
    int i = blockIdx.x * blockDim.x + tid;
    if (i >= NN) return;
    float x[10];
#pragma unroll
    for (int k = 0; k < 10; k++) x[k] = nf[i * 10 + k];
    float acc = b2s;
#pragma unroll
    for (int j = 0; j < 10; j++) {
        float h = b1[j];
#pragma unroll
        for (int k = 0; k < 10; k++) h += x[k] * w1[j * 10 + k];
        acc += elu1(h) * w2[j];
    }
    float2 c = ((const float2*)coord)[i];
    *(float4*)&g_node4[4 * i] = make_float4(c.x, c.y, acc, 0.f);
    *(float4*)&g_nodeD[4 * i] = make_float4(c.x, c.y, 0.f, 0.f);
}

// ---------------- histogram over dst ----------------
__global__ void k_hist(const int* __restrict__ ei) {
    int t = blockIdx.x * blockDim.x + threadIdx.x;
    if (t < EE) atomicAdd(&g_cnt[ei[EE + t]], 1);
}

// ---------------- 3-kernel exclusive scan ----------------
__global__ void k_scan1() {
    __shared__ int wsum[8], woff[8];
    int tid = threadIdx.x, lane = tid & 31, wrp = tid >> 5;
    int base = blockIdx.x * 1024 + tid * 4;
    int c0 = 0, c1 = 0, c2 = 0, c3 = 0;
    if (base + 0 < NN) c0 = g_cnt[base + 0];
    if (base + 1 < NN) c1 = g_cnt[base + 1];
    if (base + 2 < NN) c2 = g_cnt[base + 2];
    if (base + 3 < NN) c3 = g_cnt[base + 3];
    int tot = c0 + c1 + c2 + c3;
    int v = tot;
#pragma unroll
    for (int off = 1; off < 32; off <<= 1) {
        int o = __shfl_up_sync(~0u, v, off);
        if (lane >= off) v += o;
    }
    if (lane == 31) wsum[wrp] = v;
    __syncthreads();
    if (wrp == 0 && lane < 8) {
        int w = wsum[lane], iv = w;
#pragma unroll
        for (int off = 1; off < 8; off <<= 1) {
            int o = __shfl_up_sync(0xffu, iv, off);
            if (lane >= off) iv += o;
        }
        woff[lane] = iv - w;
    }
    __syncthreads();
    int excl = (v - tot) + woff[wrp];
    if (base + 0 < NN) g_startx[base + 0] = excl;
    if (base + 1 < NN) g_startx[base + 1] = excl + c0;
    if (base + 2 < NN) g_startx[base + 2] = excl + c0 + c1;
    if (base + 3 < NN) g_startx[base + 3] = excl + c0 + c1 + c2;
    if (tid == 255) g_bsum[blockIdx.x] = excl + tot;
}
__global__ void k_scan2(int nblk) {
    int run = 0;
    for (int i = 0; i < nblk; i++) { g_boff[i] = run; run += g_bsum[i]; }
    g_startx[NN] = EE;
}
__global__ void k_scan3() {
    int i = blockIdx.x * blockDim.x + threadIdx.x;
    if (i >= NN) return;
    int s = g_startx[i] + g_boff[i >> 10];
    g_startx[i] = s;
    g_cursor[i] = s;
}

// ---------------- bin pass: ex/ew + deg atomic + 8B record write ----------------
__global__ void k_bin(const int* __restrict__ ei) {
    int t = blockIdx.x * blockDim.x + threadIdx.x;
    if (t >= EE) return;
    int s = ei[t], d = ei[EE + t];
    float4 ns = *(const float4*)&g_node4[4 * s];
    float4 nd = *(const float4*)&g_nodeD[4 * d];
    float dx = ns.x - nd.x, dy = ns.y - nd.y;
    float gw = expf(-(dx * dx + dy * dy) * (1.0f / 1800.0f));
    float z = gw * (1.f + ns.z) - 1.f;
    float w = 0.1f + 1.9f / (1.f + expf(-z));
    bool m = (w >= 0.2f);
    float e = ns.w + nd.z;
    e = e > 0.f ? e : 0.2f * e;
    float ex = expf(e);
    __half2 p = m ? __floats2half2_rn(ex, w) : __floats2half2_rn(0.f, 0.f);
    if (m) atomicAdd(&g_deg[d], w);
    int pos = atomicAdd(&g_cursor[d], 1);
    unsigned int pb = *reinterpret_cast<unsigned int*>(&p);
    g_edata8[pos] = make_uint2((unsigned int)s, pb);
}

// ---------------- dis = rsqrt(deg) ----------------
__global__ void k_dis() {
    int i = blockIdx.x * blockDim.x + threadIdx.x;
    if (i < NN) g_dis[i] = rsqrtf(g_deg[i]);
}

// ---------------- sorted-run reduce ----------------
__global__ void k_reduce() {
    int gid = (blockIdx.x * blockDim.x + threadIdx.x) >> 4;
    int l = threadIdx.x & 15;
    int beg = gid * RCHUNK;
    if (beg >= EE) return;
    int end = min(beg + RCHUNK, EE);
    int lo = 0, hi = NN - 1;
    while (lo < hi) {
        int mid = (lo + hi + 1) >> 1;
        if (g_startx[mid] <= beg) lo = mid; else hi = mid - 1;
    }
    int n = lo;
    int nxt = g_startx[n + 1];
    float4 ag = make_float4(0.f, 0.f, 0.f, 0.f);
    float4 ac = make_float4(0.f, 0.f, 0.f, 0.f);
    float den = 0.f;
    bool dirty = false;
    uint2 rec = g_edata8[beg];
    for (int i = beg; i < end; i++) {
        uint2 cur = rec;
        if (i + 1 < end) rec = g_edata8[i + 1];
        while (i >= nxt) {
            if (dirty) {
                red4(&g_gat[(size_t)n * 64 + 4 * l], ag.x, ag.y, ag.z, ag.w);
                red4(&g_gcn[(size_t)n * 64 + 4 * l], ac.x, ac.y, ac.z, ac.w);
                if (l == 0) red1(&g_den[n], den);
                ag = make_float4(0.f, 0.f, 0.f, 0.f);
                ac = make_float4(0.f, 0.f, 0.f, 0.f);
                den = 0.f;
                dirty = false;
            }
            n++;
            nxt = g_startx[n + 1];
        }
        __half2 p; *reinterpret_cast<unsigned int*>(&p) = cur.y;
        float2 exw = __half22float2(p);
        if (exw.x == 0.f && exw.y == 0.f) continue;
        int s = (int)cur.x;
        float diss = __ldg(&g_dis[s]);
        float ewd = exw.y * diss;
        const __half2* pl = &g_xl_h[(size_t)s * 32 + 2 * l];
        float2 f0 = __half22float2(pl[0]), f1 = __half22float2(pl[1]);
        ag.x += exw.x * f0.x; ag.y += exw.x * f0.y;
        ag.z += exw.x * f1.x; ag.w += exw.x * f1.y;
        const __half2* pg = &g_xg_h[(size_t)s * 32 + 2 * l];
        float2 u0 = __half22float2(pg[0]), u1 = __half22float2(pg[1]);
        ac.x += ewd * u0.x; ac.y += ewd * u0.y;
        ac.z += ewd * u1.x; ac.w += ewd * u1.y;
        den += exw.x;
        dirty = true;
    }
    if (dirty) {
        red4(&g_gat[(size_t)n * 64 + 4 * l], ag.x, ag.y, ag.z, ag.w);
        red4(&g_gcn[(size_t)n * 64 + 4 * l], ac.x, ac.y, ac.z, ac.w);
        if (l == 0) red1(&g_den[n], den);
    }
}

// ---------------- fusion (K-split x2): finalize both branches inline -------------
__global__ void __launch_bounds__(256, 4)
k_fusion(const float* __restrict__ W1, const float* __restrict__ b1,
         const float* __restrict__ w2, const float* __restrict__ b2,
         const float* __restrict__ gat_b, const float* __restrict__ gcn_b,
         float* __restrict__ out, int nrows) {
    extern __shared__ float sm[];
    float (*Xs)[132] = (float(*)[132])sm;
    float (*Ws)[68]  = (float(*)[68])(sm + 64 * 132);
    int tid = threadIdx.x;
    int r0 = blockIdx.x * 128;
    int ty = tid >> 4, tx = tid & 15;
    int n0 = ty * 8, h0 = tx * 4;
    float acc[8][4] = {};

#pragma unroll
    for (int p = 0; p < 2; p++) {
        if (p) __syncthreads();
        {
            int h = tid & 63, kq = (tid >> 6) * 16;
            const float4* src = (const float4*)(W1 + (size_t)h * 128 + p * 64 + kq);
#pragma unroll
            for (int j = 0; j < 4; j++) {
                float4 v = src[j];
                int k = kq + 4 * j;
                Ws[k + 0][h] = v.x; Ws[k + 1][h] = v.y;
                Ws[k + 2][h] = v.z; Ws[k + 3][h] = v.w;
            }
        }
        {
            int r = tid & 127, ko = (tid >> 7) * 32;
            int rr = r0 + r;
            if (rr < nrows) {
                if (p == 0) {  // GAT half: elu((acc + exself*xl)/den + b)
                    float inv = 1.f / g_den[rr];
                    float exs = g_exself[rr];
                    const float4*  pa = (const float4*)(g_gat + (size_t)rr * 64) + (ko >> 2);
                    const __half2* px = &g_xl_h[(size_t)rr * 32 + (ko >> 1)];
                    const float4*  pb = (const float4*)gat_b + (ko >> 2);
#pragma unroll
                    for (int j = 0; j < 8; j++) {
                        float4 a = pa[j], b = pb[j];
                        float2 x0 = __half22float2(px[2 * j]);
                        float2 x1 = __half22float2(px[2 * j + 1]);
                        int k = ko + 4 * j;
                        Xs[k + 0][r] = elu1((a.x + exs * x0.x) * inv + b.x);
                        Xs[k + 1][r] = elu1((a.y + exs * x0.y) * inv + b.y);
                        Xs[k + 2][r] = elu1((a.z + exs * x1.x) * inv + b.z);
                        Xs[k + 3][r] = elu1((a.w + exs * x1.y) * inv + b.w);
                    }
                } else {       // GCN half: relu(dis*(acc + dis*xg) + b)
                    float dis = g_dis[rr];
                    const float4*  pa = (const float4*)(g_gcn + (size_t)rr * 64) + (ko >> 2);
                    const __half2* px = &g_xg_h[(size_t)rr * 32 + (ko >> 1)];
                    const float4*  pb = (const float4*)gcn_b + (ko >> 2);
#pragma unroll
                    for (int j = 0; j < 8; j++) {
                        float4 a = pa[j], b = pb[j];
                        float2 x0 = __half22float2(px[2 * j]);
                        float2 x1 = __half22float2(px[2 * j + 1]);
                        int k = ko + 4 * j;
                        Xs[k + 0][r] = fmaxf(dis * (a.x + dis * x0.x) + b.x, 0.f);
                        Xs[k + 1][r] = fmaxf(dis * (a.y + dis * x0.y) + b.y, 0.f);
                        Xs[k + 2][r] = fmaxf(dis * (a.z + dis * x1.x) + b.z, 0.f);
                        Xs[k + 3][r] = fmaxf(dis * (a.w + dis * x1.y) + b.w, 0.f);
                    }
                }
            } else {
#pragma unroll
                for (int j = 0; j < 32; j++) Xs[ko + j][r] = 0.f;
            }
        }
        __syncthreads();
#pragma unroll 4
        for (int k = 0; k < 64; k++) {
            float4 x0 = *(const float4*)&Xs[k][n0];
            float4 x1 = *(const float4*)&Xs[k][n0 + 4];
            float4 wv = *(const float4*)&Ws[k][h0];
            float xs[8] = {x0.x, x0.y, x0.z, x0.w, x1.x, x1.y, x1.z, x1.w};
            float ws[4] = {wv.x, wv.y, wv.z, wv.w};
#pragma unroll
            for (int i = 0; i < 8; i++)
#pragma unroll
                for (int j = 0; j < 4; j++) acc[i][j] += xs[i] * ws[j];
        }
    }

    float b1v[4], w2v[4];
#pragma unroll
    for (int j = 0; j < 4; j++) { b1v[j] = b1[h0 + j]; w2v[j] = w2[h0 + j]; }
    float part[8];
#pragma unroll
    for (int i = 0; i < 8; i++) {
        float p = 0.f;
#pragma unroll
        for (int j = 0; j < 4; j++) p += fmaxf(acc[i][j] + b1v[j], 0.f) * w2v[j];
        part[i] = p;
    }
#pragma unroll
    for (int off = 8; off >= 1; off >>= 1)
#pragma unroll
        for (int i = 0; i < 8; i++) part[i] += __shfl_down_sync(0xffffffffu, part[i], off, 16);
    if (tx == 0) {
        float bb = b2[0];
#pragma unroll
        for (int i = 0; i < 8; i++) {
            int r = r0 + n0 + i;
            if (r < nrows) out[r] = part[i] + bb;
        }
    }
}

// ---------------- launch ----------------
extern "C" void kernel_launch(void* const* d_in, const int* in_sizes, int n_in,
                              void* d_out, int out_size) {
    const float* x_local  = (const float*)d_in[0];
    const float* x_global = (const float*)d_in[1];
    const float* nf       = (const float*)d_in[2];
    const float* coord    = (const float*)d_in[3];
    const int*   ei       = (const int*)d_in[4];
    const float* fc1w     = (const float*)d_in[5];
    const float* fc1b     = (const float*)d_in[6];
    const float* fc2w     = (const float*)d_in[7];
    const float* fc2b     = (const float*)d_in[8];
    const float* gat_w    = (const float*)d_in[9];
    const float* att_s    = (const float*)d_in[10];
    const float* att_d    = (const float*)d_in[11];
    const float* gat_b    = (const float*)d_in[12];
    const float* gcn_w    = (const float*)d_in[13];
    const float* gcn_b    = (const float*)d_in[14];
    const float* fus_w1   = (const float*)d_in[15];
    const float* fus_b1   = (const float*)d_in[16];
    const float* fus_w2   = (const float*)d_in[17];
    const float* fus_b2   = (const float*)d_in[18];
    float* out = (float*)d_out;

    const int SMEM_G = (64 * 132 + 64 * 68) * (int)sizeof(float);  // 51200
    cudaFuncSetAttribute(k_gemm,   cudaFuncAttributeMaxDynamicSharedMemorySize, SMEM_G);
    cudaFuncSetAttribute(k_fusion, cudaFuncAttributeMaxDynamicSharedMemorySize, SMEM_G);

    float *pgat, *pgcn;
    __half2 *pxlh, *pxgh;
    void *pcnt;
    cudaGetSymbolAddress((void**)&pxlh, g_xl_h);
    cudaGetSymbolAddress((void**)&pxgh, g_xg_h);
    cudaGetSymbolAddress((void**)&pgat, g_gat);
    cudaGetSymbolAddress((void**)&pgcn, g_gcn);
    cudaGetSymbolAddress(&pcnt, g_cnt);

    const int NB_N   = (NN + 255) / 256;                 // 196
    const int NB_E   = (EE + 255) / 256;                 // 6250
    const int NB_G   = (NN + 127) / 128;                 // 391
    const int NSCAN  = (NN + 1023) / 1024;               // 49
    const int NGROUP = (EE + RCHUNK - 1) / RCHUNK;       // 25000
    const int NB_R   = (NGROUP * 16 + 255) / 256;        // 1563

    cudaMemsetAsync(pcnt, 0, NN * sizeof(int));
    cudaMemsetAsync(pgat, 0, (size_t)NN * 64 * sizeof(float));
    cudaMemsetAsync(pgcn, 0, (size_t)NN * 64 * sizeof(float));
    k_hist<<<NB_E, 256>>>(ei);
    k_nind<<<NB_N, 256>>>(nf, coord, fc1w, fc1b, fc2w, fc2b);
    k_gemm<<<NB_G, 256, SMEM_G>>>(x_local, gat_w, pxlh, att_s, att_d, NN);
    k_gemm<<<NB_G, 256, SMEM_G>>>(x_global, gcn_w, pxgh, nullptr, nullptr, NN);
    k_scan1<<<NSCAN, 256>>>();
    k_scan2<<<1, 1>>>(NSCAN);
    k_scan3<<<NB_N, 256>>>();
    k_bin<<<NB_E, 256>>>(ei);
    k_dis<<<NB_N, 256>>>();
    k_reduce<<<NB_R, 256>>>();
    k_fusion<<<NB_G, 256, SMEM_G>>>(fus_w1, fus_b1, fus_w2, fus_b2, gat_b, gcn_b, out, NN);
}

// round 7
// speedup vs baseline: 1.6399x; 1.0484x over previous
#include <cuda_runtime.h>
#include <cuda_fp16.h>
#include <math.h>

#define NN 50000
#define EE 1600000
#define RCHUNK 64

// ---------------- scratch ----------------
__device__ __align__(16) __half2 g_xl_h[NN * 32];  // x_local @ gat_w^T (fp16)
__device__ __align__(16) __half2 g_xg_h[NN * 32];  // x_global @ gcn_w^T (fp16)
__device__ __align__(16) float g_gat[NN * 64];
__device__ __align__(16) float g_gcn[NN * 64];
__device__ __align__(16) float g_node4[NN * 4];    // {cx, cy, nind, asrc}
__device__ __align__(16) float g_nodeD[NN * 4];    // {cx, cy, adst, 0}
__device__ float g_exself[NN];
__device__ float g_den[NN];
__device__ float g_deg[NN];
__device__ float g_dis[NN];
__device__ int   g_cnt[NN];
__device__ int   g_startx[NN + 1];
__device__ int   g_cursor[NN];
__device__ int   g_bsum[64];
__device__ int   g_boff[64];
__device__ __align__(8) uint2 g_edata8[EE];  // {src, half2(ex,ew)} binned by dst

// ---------------- helpers ----------------
__device__ __forceinline__ void red4(float* p, float a, float b, float c, float d) {
    asm volatile("red.global.add.v4.f32 [%0], {%1,%2,%3,%4};"
                 :: "l"(p), "f"(a), "f"(b), "f"(c), "f"(d) : "memory");
}
__device__ __forceinline__ void red1(float* p, float v) {
    asm volatile("red.global.add.f32 [%0], %1;" :: "l"(p), "f"(v) : "memory");
}
__device__ __forceinline__ float elu1(float v) { return v > 0.f ? v : (expf(v) - 1.f); }

#define MMA16816(ac, a, b)                                                        \
    asm volatile(                                                                 \
        "mma.sync.aligned.m16n8k16.row.col.f32.f16.f16.f32 "                      \
        "{%0,%1,%2,%3}, {%4,%5,%6,%7}, {%8,%9}, {%0,%1,%2,%3};"                   \
        : "+f"((ac)[0]), "+f"((ac)[1]), "+f"((ac)[2]), "+f"((ac)[3])              \
        : "r"((a)[0]), "r"((a)[1]), "r"((a)[2]), "r"((a)[3]),                     \
          "r"((b)[0]), "r"((b)[1]))

// ---------------- tensor-core GEMM with hi/lo fp16 split ----------------
// out[n][64] = sum_k X[n][k]*W[h][k]. 128 rows/block, 256 threads (8 warps).
// X = Xh + Xl, W = Wh + Wl (fp16 splits); acc = XhWh + XlWh + XhWl (fp32).
// smem: Xh,Xl [128][136] + Wh,Wl [64][136] halves = 104448 B.
#define XS 136
__global__ void k_gemm(const float* __restrict__ X, const float* __restrict__ W,
                       __half2* __restrict__ outh,
                       const float* __restrict__ att_s, const float* __restrict__ att_d,
                       int nrows) {
    extern __shared__ __half smh[];
    __half* Xh = smh;
    __half* Xl = smh + 128 * XS;
    __half* Wh = smh + 256 * XS;
    __half* Wl = smh + 256 * XS + 64 * XS;
    __shared__ float s_as[64], s_ad[64];
    int tid = threadIdx.x;
    int r0 = blockIdx.x * 128;
    if (att_s) {
        if (tid < 64) s_as[tid] = att_s[tid];
        else if (tid < 128) s_ad[tid - 64] = att_d[tid - 64];
    }
    // load X -> Xh/Xl
    {
        int r = tid & 127, kb = (tid >> 7) * 64;
        int rr = r0 + r;
        const float4* src = (const float4*)(X + (size_t)rr * 128 + kb);
#pragma unroll
        for (int j = 0; j < 16; j++) {
            float4 v = (rr < nrows) ? src[j] : make_float4(0.f, 0.f, 0.f, 0.f);
            int k = kb + 4 * j;
            __half h0 = __float2half_rn(v.x), h1 = __float2half_rn(v.y);
            __half h2 = __float2half_rn(v.z), h3 = __float2half_rn(v.w);
            *(__half2*)&Xh[r * XS + k]     = __halves2half2(h0, h1);
            *(__half2*)&Xh[r * XS + k + 2] = __halves2half2(h2, h3);
            *(__half2*)&Xl[r * XS + k] = __halves2half2(
                __float2half_rn(v.x - __half2float(h0)),
                __float2half_rn(v.y - __half2float(h1)));
            *(__half2*)&Xl[r * XS + k + 2] = __halves2half2(
                __float2half_rn(v.z - __half2float(h2)),
                __float2half_rn(v.w - __half2float(h3)));
        }
    }
    // load W -> Wh/Wl
    {
        int h = tid & 63, kb = (tid >> 6) * 32;
        const float4* src = (const float4*)(W + (size_t)h * 128 + kb);
#pragma unroll
        for (int j = 0; j < 8; j++) {
            float4 v = src[j];
            int k = kb + 4 * j;
            __half h0 = __float2half_rn(v.x), h1 = __float2half_rn(v.y);
            __half h2 = __float2half_rn(v.z), h3 = __float2half_rn(v.w);
            *(__half2*)&Wh[h * XS + k]     = __halves2half2(h0, h1);
            *(__half2*)&Wh[h * XS + k + 2] = __halves2half2(h2, h3);
            *(__half2*)&Wl[h * XS + k] = __halves2half2(
                __float2half_rn(v.x - __half2float(h0)),
                __float2half_rn(v.y - __half2float(h1)));
            *(__half2*)&Wl[h * XS + k + 2] = __halves2half2(
                __float2half_rn(v.z - __half2float(h2)),
                __float2half_rn(v.w - __half2float(h3)));
        }
    }
    __syncthreads();

    int wid = tid >> 5, lane = tid & 31;
    int m0 = wid * 16;
    int g = lane >> 2, c = (lane & 3) * 2;
    float acc[8][4] = {};

#pragma unroll
    for (int kk = 0; kk < 128; kk += 16) {
        unsigned ah[4], al[4];
        ah[0] = *(const unsigned*)&Xh[(m0 + g) * XS + kk + c];
        ah[1] = *(const unsigned*)&Xh[(m0 + g + 8) * XS + kk + c];
        ah[2] = *(const unsigned*)&Xh[(m0 + g) * XS + kk + c + 8];
        ah[3] = *(const unsigned*)&Xh[(m0 + g + 8) * XS + kk + c + 8];
        al[0] = *(const unsigned*)&Xl[(m0 + g) * XS + kk + c];
        al[1] = *(const unsigned*)&Xl[(m0 + g + 8) * XS + kk + c];
        al[2] = *(const unsigned*)&Xl[(m0 + g) * XS + kk + c + 8];
        al[3] = *(const unsigned*)&Xl[(m0 + g + 8) * XS + kk + c + 8];
#pragma unroll
        for (int nt = 0; nt < 8; nt++) {
            int n = nt * 8 + g;
            unsigned bh[2], bl[2];
            bh[0] = *(const unsigned*)&Wh[n * XS + kk + c];
            bh[1] = *(const unsigned*)&Wh[n * XS + kk + c + 8];
            bl[0] = *(const unsigned*)&Wl[n * XS + kk + c];
            bl[1] = *(const unsigned*)&Wl[n * XS + kk + c + 8];
            MMA16816(acc[nt], ah, bh);
            MMA16816(acc[nt], al, bh);
            MMA16816(acc[nt], ah, bl);
        }
    }

    int ra = r0 + m0 + g, rb = ra + 8;
    __half* oh = (__half*)outh;
#pragma unroll
    for (int nt = 0; nt < 8; nt++) {
        int cb = nt * 8 + c;
        if (ra < nrows)
            *(__half2*)&oh[(size_t)ra * 64 + cb] = __floats2half2_rn(acc[nt][0], acc[nt][1]);
        if (rb < nrows)
            *(__half2*)&oh[(size_t)rb * 64 + cb] = __floats2half2_rn(acc[nt][2], acc[nt][3]);
    }

    if (att_s) {
        float pa_s = 0.f, pa_d = 0.f, pb_s = 0.f, pb_d = 0.f;
#pragma unroll
        for (int nt = 0; nt < 8; nt++) {
            int cb = nt * 8 + c;
            pa_s += acc[nt][0] * s_as[cb] + acc[nt][1] * s_as[cb + 1];
            pa_d += acc[nt][0] * s_ad[cb] + acc[nt][1] * s_ad[cb + 1];
            pb_s += acc[nt][2] * s_as[cb] + acc[nt][3] * s_as[cb + 1];
            pb_d += acc[nt][2] * s_ad[cb] + acc[nt][3] * s_ad[cb + 1];
        }
        pa_s += __shfl_down_sync(~0u, pa_s, 2, 4); pa_s += __shfl_down_sync(~0u, pa_s, 1, 4);
        pa_d += __shfl_down_sync(~0u, pa_d, 2, 4); pa_d += __shfl_down_sync(~0u, pa_d, 1, 4);
        pb_s += __shfl_down_sync(~0u, pb_s, 2, 4); pb_s += __shfl_down_sync(~0u, pb_s, 1, 4);
        pb_d += __shfl_down_sync(~0u, pb_d, 2, 4); pb_d += __shfl_down_sync(~0u, pb_d, 1, 4);
        if ((lane & 3) == 0) {
            if (ra < nrows) {
                g_node4[4 * ra + 3] = pa_s;
                g_nodeD[4 * ra + 2] = pa_d;
                float e = pa_s + pa_d;
                e = e > 0.f ? e : 0.2f * e;
                float ex = expf(e);
                g_exself[ra] = ex; g_den[ra] = ex; g_deg[ra] = 1.f;
            }
            if (rb < nrows) {
                g_node4[4 * rb + 3] = pb_s;
                g_nodeD[4 * rb + 2] = pb_d;
                float e = pb_s + pb_d;
                e = e > 0.f ? e : 0.2f * e;
                float ex = expf(e);
                g_exself[rb] = ex; g_den[rb] = ex; g_deg[rb] = 1.f;
            }
        }
    }
}

// ---------------- per-node noise MLP + coord packing ----------------
__global__ void k_nind(const float* __restrict__ nf, const float* __restrict__ coord,
                       const float* __restrict__ fc1w, const float* __restrict__ fc1b,
                       const float* __restrict__ fc2w, const float* __restrict__ fc2b) {
    __shared__ float w1[100], b1[10], w2[10], b2s;
    int tid = threadIdx.x;
    if (tid < 100) w1[tid] = fc1w[tid];
    if (tid < 10) { b1[tid] = fc1b[tid]; w2[tid] = fc2w[tid]; }
    if (tid == 0) b2s = fc2b[0];
    __syncthreads();
    int i = blockIdx.x * blockDim.x + tid;
    if (i >= NN) return;
    float x[10];
#pragma unroll
    for (int k = 0; k < 10; k++) x[k] = nf[i * 10 + k];
    float acc = b2s;
#pragma unroll
    for (int j = 0; j < 10; j++) {
        float h = b1[j];
#pragma unroll
        for (int k = 0; k < 10; k++) h += x[k] * w1[j * 10 + k];
        acc += elu1(h) * w2[j];
    }
    float2 c = ((const float2*)coord)[i];
    *(float4*)&g_node4[4 * i] = make_float4(c.x, c.y, acc, 0.f);
    *(float4*)&g_nodeD[4 * i] = make_float4(c.x, c.y, 0.f, 0.f);
}

// ---------------- histogram over dst ----------------
__global__ void k_hist(const int* __restrict__ ei) {
    int t = blockIdx.x * blockDim.x + threadIdx.x;
    if (t < EE) atomicAdd(&g_cnt[ei[EE + t]], 1);
}

// ---------------- 3-kernel exclusive scan ----------------
__global__ void k_scan1() {
    __shared__ int wsum[8], woff[8];
    int tid = threadIdx.x, lane = tid & 31, wrp = tid >> 5;
    int base = blockIdx.x * 1024 + tid * 4;
    int c0 = 0, c1 = 0, c2 = 0, c3 = 0;
    if (base + 0 < NN) c0 = g_cnt[base + 0];
    if (base + 1 < NN) c1 = g_cnt[base + 1];
    if (base + 2 < NN) c2 = g_cnt[base + 2];
    if (base + 3 < NN) c3 = g_cnt[base + 3];
    int tot = c0 + c1 + c2 + c3;
    int v = tot;
#pragma unroll
    for (int off = 1; off < 32; off <<= 1) {
        int o = __shfl_up_sync(~0u, v, off);
        if (lane >= off) v += o;
    }
    if (lane == 31) wsum[wrp] = v;
    __syncthreads();
    if (wrp == 0 && lane < 8) {
        int w = wsum[lane], iv = w;
#pragma unroll
        for (int off = 1; off < 8; off <<= 1) {
            int o = __shfl_up_sync(0xffu, iv, off);
            if (lane >= off) iv += o;
        }
        woff[lane] = iv - w;
    }
    __syncthreads();
    int excl = (v - tot) + woff[wrp];
    if (base + 0 < NN) g_startx[base + 0] = excl;
    if (base + 1 < NN) g_startx[base + 1] = excl + c0;
    if (base + 2 < NN) g_startx[base + 2] = excl + c0 + c1;
    if (base + 3 < NN) g_startx[base + 3] = excl + c0 + c1 + c2;
    if (tid == 255) g_bsum[blockIdx.x] = excl + tot;
}
__global__ void k_scan2(int nblk) {
    int run = 0;
    for (int i = 0; i < nblk; i++) { g_boff[i] = run; run += g_bsum[i]; }
    g_startx[NN] = EE;
}
__global__ void k_scan3() {
    int i = blockIdx.x * blockDim.x + threadIdx.x;
    if (i >= NN) return;
    int s = g_startx[i] + g_boff[i >> 10];
    g_startx[i] = s;
    g_cursor[i] = s;
}

// ---------------- bin pass: ex/ew + deg atomic + 8B record write ----------------
__global__ void k_bin(const int* __restrict__ ei) {
    int t = blockIdx.x * blockDim.x + threadIdx.x;
    if (t >= EE) return;
    int s = ei[t], d = ei[EE + t];
    float4 ns = *(const float4*)&g_node4[4 * s];
    float4 nd = *(const float4*)&g_nodeD[4 * d];
    float dx = ns.x - nd.x, dy = ns.y - nd.y;
    float gw = expf(-(dx * dx + dy * dy) * (1.0f / 1800.0f));
    float z = gw * (1.f + ns.z) - 1.f;
    float w = 0.1f + 1.9f / (1.f + expf(-z));
    bool m = (w >= 0.2f);
    float e = ns.w + nd.z;
    e = e > 0.f ? e : 0.2f * e;
    float ex = expf(e);
    __half2 p = m ? __floats2half2_rn(ex, w) : __floats2half2_rn(0.f, 0.f);
    if (m) atomicAdd(&g_deg[d], w);
    int pos = atomicAdd(&g_cursor[d], 1);
    unsigned int pb = *reinterpret_cast<unsigned int*>(&p);
    g_edata8[pos] = make_uint2((unsigned int)s, pb);
}

// ---------------- dis = rsqrt(deg) ----------------
__global__ void k_dis() {
    int i = blockIdx.x * blockDim.x + threadIdx.x;
    if (i < NN) g_dis[i] = rsqrtf(g_deg[i]);
}

// ---------------- sorted-run reduce ----------------
__global__ void k_reduce() {
    int gid = (blockIdx.x * blockDim.x + threadIdx.x) >> 4;
    int l = threadIdx.x & 15;
    int beg = gid * RCHUNK;
    if (beg >= EE) return;
    int end = min(beg + RCHUNK, EE);
    int lo = 0, hi = NN - 1;
    while (lo < hi) {
        int mid = (lo + hi + 1) >> 1;
        if (g_startx[mid] <= beg) lo = mid; else hi = mid - 1;
    }
    int n = lo;
    int nxt = g_startx[n + 1];
    float4 ag = make_float4(0.f, 0.f, 0.f, 0.f);
    float4 ac = make_float4(0.f, 0.f, 0.f, 0.f);
    float den = 0.f;
    bool dirty = false;
    uint2 rec = g_edata8[beg];
    for (int i = beg; i < end; i++) {
        uint2 cur = rec;
        if (i + 1 < end) rec = g_edata8[i + 1];
        while (i >= nxt) {
            if (dirty) {
                red4(&g_gat[(size_t)n * 64 + 4 * l], ag.x, ag.y, ag.z, ag.w);
                red4(&g_gcn[(size_t)n * 64 + 4 * l], ac.x, ac.y, ac.z, ac.w);
                if (l == 0) red1(&g_den[n], den);
                ag = make_float4(0.f, 0.f, 0.f, 0.f);
                ac = make_float4(0.f, 0.f, 0.f, 0.f);
                den = 0.f;
                dirty = false;
            }
            n++;
            nxt = g_startx[n + 1];
        }
        __half2 p; *reinterpret_cast<unsigned int*>(&p) = cur.y;
        float2 exw = __half22float2(p);
        if (exw.x == 0.f && exw.y == 0.f) continue;
        int s = (int)cur.x;
        float diss = __ldg(&g_dis[s]);
        float ewd = exw.y * diss;
        const __half2* pl = &g_xl_h[(size_t)s * 32 + 2 * l];
        float2 f0 = __half22float2(pl[0]), f1 = __half22float2(pl[1]);
        ag.x += exw.x * f0.x; ag.y += exw.x * f0.y;
        ag.z += exw.x * f1.x; ag.w += exw.x * f1.y;
        const __half2* pg = &g_xg_h[(size_t)s * 32 + 2 * l];
        float2 u0 = __half22float2(pg[0]), u1 = __half22float2(pg[1]);
        ac.x += ewd * u0.x; ac.y += ewd * u0.y;
        ac.z += ewd * u1.x; ac.w += ewd * u1.y;
        den += exw.x;
        dirty = true;
    }
    if (dirty) {
        red4(&g_gat[(size_t)n * 64 + 4 * l], ag.x, ag.y, ag.z, ag.w);
        red4(&g_gcn[(size_t)n * 64 + 4 * l], ac.x, ac.y, ac.z, ac.w);
        if (l == 0) red1(&g_den[n], den);
    }
}

// ---------------- fusion (K-split x2): finalize both branches inline -------------
__global__ void __launch_bounds__(256, 4)
k_fusion(const float* __restrict__ W1, const float* __restrict__ b1,
         const float* __restrict__ w2, const float* __restrict__ b2,
         const float* __restrict__ gat_b, const float* __restrict__ gcn_b,
         float* __restrict__ out, int nrows) {
    extern __shared__ float sm[];
    float (*Xs)[132] = (float(*)[132])sm;
    float (*Ws)[68]  = (float(*)[68])(sm + 64 * 132);
    int tid = threadIdx.x;
    int r0 = blockIdx.x * 128;
    int ty = tid >> 4, tx = tid & 15;
    int n0 = ty * 8, h0 = tx * 4;
    float acc[8][4] = {};

#pragma unroll
    for (int p = 0; p < 2; p++) {
        if (p) __syncthreads();
        {
            int h = tid & 63, kq = (tid >> 6) * 16;
            const float4* src = (const float4*)(W1 + (size_t)h * 128 + p * 64 + kq);
#pragma unroll
            for (int j = 0; j < 4; j++) {
                float4 v = src[j];
                int k = kq + 4 * j;
                Ws[k + 0][h] = v.x; Ws[k + 1][h] = v.y;
                Ws[k + 2][h] = v.z; Ws[k + 3][h] = v.w;
            }
        }
        {
            int r = tid & 127, ko = (tid >> 7) * 32;
            int rr = r0 + r;
            if (rr < nrows) {
                if (p == 0) {
                    float inv = 1.f / g_den[rr];
                    float exs = g_exself[rr];
                    const float4*  pa = (const float4*)(g_gat + (size_t)rr * 64) + (ko >> 2);
                    const __half2* px = &g_xl_h[(size_t)rr * 32 + (ko >> 1)];
                    const float4*  pb = (const float4*)gat_b + (ko >> 2);
#pragma unroll
                    for (int j = 0; j < 8; j++) {
                        float4 a = pa[j], b = pb[j];
                        float2 x0 = __half22float2(px[2 * j]);
                        float2 x1 = __half22float2(px[2 * j + 1]);
                        int k = ko + 4 * j;
                        Xs[k + 0][r] = elu1((a.x + exs * x0.x) * inv + b.x);
                        Xs[k + 1][r] = elu1((a.y + exs * x0.y) * inv + b.y);
                        Xs[k + 2][r] = elu1((a.z + exs * x1.x) * inv + b.z);
                        Xs[k + 3][r] = elu1((a.w + exs * x1.y) * inv + b.w);
                    }
                } else {
                    float dis = g_dis[rr];
                    const float4*  pa = (const float4*)(g_gcn + (size_t)rr * 64) + (ko >> 2);
                    const __half2* px = &g_xg_h[(size_t)rr * 32 + (ko >> 1)];
                    const float4*  pb = (const float4*)gcn_b + (ko >> 2);
#pragma unroll
                    for (int j = 0; j < 8; j++) {
                        float4 a = pa[j], b = pb[j];
                        float2 x0 = __half22float2(px[2 * j]);
                        float2 x1 = __half22float2(px[2 * j + 1]);
                        int k = ko + 4 * j;
                        Xs[k + 0][r] = fmaxf(dis * (a.x + dis * x0.x) + b.x, 0.f);
                        Xs[k + 1][r] = fmaxf(dis * (a.y + dis * x0.y) + b.y, 0.f);
                        Xs[k + 2][r] = fmaxf(dis * (a.z + dis * x1.x) + b.z, 0.f);
                        Xs[k + 3][r] = fmaxf(dis * (a.w + dis * x1.y) + b.w, 0.f);
                    }
                }
            } else {
#pragma unroll
                for (int j = 0; j < 32; j++) Xs[ko + j][r] = 0.f;
            }
        }
        __syncthreads();
#pragma unroll 4
        for (int k = 0; k < 64; k++) {
            float4 x0 = *(const float4*)&Xs[k][n0];
            float4 x1 = *(const float4*)&Xs[k][n0 + 4];
            float4 wv = *(const float4*)&Ws[k][h0];
            float xs[8] = {x0.x, x0.y, x0.z, x0.w, x1.x, x1.y, x1.z, x1.w};
            float ws[4] = {wv.x, wv.y, wv.z, wv.w};
#pragma unroll
            for (int i = 0; i < 8; i++)
#pragma unroll
                for (int j = 0; j < 4; j++) acc[i][j] += xs[i] * ws[j];
        }
    }

    float b1v[4], w2v[4];
#pragma unroll
    for (int j = 0; j < 4; j++) { b1v[j] = b1[h0 + j]; w2v[j] = w2[h0 + j]; }
    float part[8];
#pragma unroll
    for (int i = 0; i < 8; i++) {
        float p = 0.f;
#pragma unroll
        for (int j = 0; j < 4; j++) p += fmaxf(acc[i][j] + b1v[j], 0.f) * w2v[j];
        part[i] = p;
    }
#pragma unroll
    for (int off = 8; off >= 1; off >>= 1)
#pragma unroll
        for (int i = 0; i < 8; i++) part[i] += __shfl_down_sync(0xffffffffu, part[i], off, 16);
    if (tx == 0) {
        float bb = b2[0];
#pragma unroll
        for (int i = 0; i < 8; i++) {
            int r = r0 + n0 + i;
            if (r < nrows) out[r] = part[i] + bb;
        }
    }
}

// ---------------- launch ----------------
extern "C" void kernel_launch(void* const* d_in, const int* in_sizes, int n_in,
                              void* d_out, int out_size) {
    const float* x_local  = (const float*)d_in[0];
    const float* x_global = (const float*)d_in[1];
    const float* nf       = (const float*)d_in[2];
    const float* coord    = (const float*)d_in[3];
    const int*   ei       = (const int*)d_in[4];
    const float* fc1w     = (const float*)d_in[5];
    const float* fc1b     = (const float*)d_in[6];
    const float* fc2w     = (const float*)d_in[7];
    const float* fc2b     = (const float*)d_in[8];
    const float* gat_w    = (const float*)d_in[9];
    const float* att_s    = (const float*)d_in[10];
    const float* att_d    = (const float*)d_in[11];
    const float* gat_b    = (const float*)d_in[12];
    const float* gcn_w    = (const float*)d_in[13];
    const float* gcn_b    = (const float*)d_in[14];
    const float* fus_w1   = (const float*)d_in[15];
    const float* fus_b1   = (const float*)d_in[16];
    const float* fus_w2   = (const float*)d_in[17];
    const float* fus_b2   = (const float*)d_in[18];
    float* out = (float*)d_out;

    const int SMEM_MMA = (256 * XS + 128 * XS) * (int)sizeof(__half);  // 104448
    const int SMEM_F   = (64 * 132 + 64 * 68) * (int)sizeof(float);    // 51200
    cudaFuncSetAttribute(k_gemm,   cudaFuncAttributeMaxDynamicSharedMemorySize, SMEM_MMA);
    cudaFuncSetAttribute(k_fusion, cudaFuncAttributeMaxDynamicSharedMemorySize, SMEM_F);

    float *pgat, *pgcn;
    __half2 *pxlh, *pxgh;
    void *pcnt;
    cudaGetSymbolAddress((void**)&pxlh, g_xl_h);
    cudaGetSymbolAddress((void**)&pxgh, g_xg_h);
    cudaGetSymbolAddress((void**)&pgat, g_gat);
    cudaGetSymbolAddress((void**)&pgcn, g_gcn);
    cudaGetSymbolAddress(&pcnt, g_cnt);

    const int NB_N   = (NN + 255) / 256;                 // 196
    const int NB_E   = (EE + 255) / 256;                 // 6250
    const int NB_G   = (NN + 127) / 128;                 // 391
    const int NSCAN  = (NN + 1023) / 1024;               // 49
    const int NGROUP = (EE + RCHUNK - 1) / RCHUNK;       // 25000
    const int NB_R   = (NGROUP * 16 + 255) / 256;        // 1563

    cudaMemsetAsync(pcnt, 0, NN * sizeof(int));
    cudaMemsetAsync(pgat, 0, (size_t)NN * 64 * sizeof(float));
    cudaMemsetAsync(pgcn, 0, (size_t)NN * 64 * sizeof(float));
    k_hist<<<NB_E, 256>>>(ei);
    k_nind<<<NB_N, 256>>>(nf, coord, fc1w, fc1b, fc2w, fc2b);
    k_gemm<<<NB_G, 256, SMEM_MMA>>>(x_local, gat_w, pxlh, att_s, att_d, NN);
    k_gemm<<<NB_G, 256, SMEM_MMA>>>(x_global, gcn_w, pxgh, nullptr, nullptr, NN);
    k_scan1<<<NSCAN, 256>>>();
    k_scan2<<<1, 1>>>(NSCAN);
    k_scan3<<<NB_N, 256>>>();
    k_bin<<<NB_E, 256>>>(ei);
    k_dis<<<NB_N, 256>>>();
    k_reduce<<<NB_R, 256>>>();
    k_fusion<<<NB_G, 256, SMEM_F>>>(fus_w1, fus_b1, fus_w2, fus_b2, gat_b, gcn_b, out, NN);
}